// round 1
// baseline (speedup 1.0000x reference)
#include <cuda_runtime.h>
#include <math.h>

// Problem constants
#define BB   4
#define SS   1024
#define DD   1024
#define HH   16
#define DH   64
#define DFF  4096
#define MM   (BB*SS)          // 4096 rows
#define LN_EPS 1e-5f

// -------------------- scratch (static device globals; no runtime alloc) ----
__device__ float g_q[MM*DD];
__device__ float g_k[MM*DD];
__device__ float g_v[MM*DD];
__device__ float g_ctx[MM*DD];
__device__ float g_mha[MM*DD];
__device__ float g_res1[MM*DD];
__device__ float g_res2[MM*DD];
__device__ float g_ffn[(size_t)MM*DFF];

// ============================================================================
// SGEMM: C[M,N] = A[M,K] @ W[K,N] + bias[N], optional ReLU.
// 128x128 block tile, BK=8, 256 threads, 8x8 per thread. M,N %128==0, K%8==0.
// ============================================================================
template<bool RELU>
__global__ __launch_bounds__(256) void sgemm_bias(
    const float* __restrict__ A, const float* __restrict__ W,
    const float* __restrict__ bias, float* __restrict__ C,
    int M, int N, int K)
{
    __shared__ float As[8][128];
    __shared__ float Bs[8][128];
    const int tid = threadIdx.x;
    const int tx = tid & 15, ty = tid >> 4;
    const int row0 = blockIdx.y * 128, col0 = blockIdx.x * 128;

    const int arow = tid >> 1,  ak4 = (tid & 1) * 4;   // A tile: 128 rows x 8
    const int brow = tid >> 5,  bc4 = (tid & 31) * 4;  // W tile: 8 rows x 128

    float acc[8][8];
#pragma unroll
    for (int i = 0; i < 8; i++)
#pragma unroll
        for (int j = 0; j < 8; j++) acc[i][j] = 0.f;

    const float* Aptr = A + (size_t)(row0 + arow) * K + ak4;
    const float* Wptr = W + (size_t)brow * N + col0 + bc4;

    for (int k0 = 0; k0 < K; k0 += 8) {
        float4 a = *(const float4*)(Aptr + k0);
        As[ak4 + 0][arow] = a.x;
        As[ak4 + 1][arow] = a.y;
        As[ak4 + 2][arow] = a.z;
        As[ak4 + 3][arow] = a.w;
        float4 b = *(const float4*)(Wptr + (size_t)k0 * N);
        *(float4*)&Bs[brow][bc4] = b;
        __syncthreads();
#pragma unroll
        for (int k = 0; k < 8; k++) {
            float ar[8], br[8];
#pragma unroll
            for (int i = 0; i < 8; i++) ar[i] = As[k][ty * 8 + i];
#pragma unroll
            for (int j = 0; j < 8; j++) br[j] = Bs[k][tx * 8 + j];
#pragma unroll
            for (int i = 0; i < 8; i++)
#pragma unroll
                for (int j = 0; j < 8; j++)
                    acc[i][j] = fmaf(ar[i], br[j], acc[i][j]);
        }
        __syncthreads();
    }

    float bv[8];
#pragma unroll
    for (int j = 0; j < 8; j++) bv[j] = bias[col0 + tx * 8 + j];

#pragma unroll
    for (int i = 0; i < 8; i++) {
        size_t r = (size_t)(row0 + ty * 8 + i) * N + col0 + tx * 8;
#pragma unroll
        for (int j4 = 0; j4 < 2; j4++) {
            float4 o;
            o.x = acc[i][j4 * 4 + 0] + bv[j4 * 4 + 0];
            o.y = acc[i][j4 * 4 + 1] + bv[j4 * 4 + 1];
            o.z = acc[i][j4 * 4 + 2] + bv[j4 * 4 + 2];
            o.w = acc[i][j4 * 4 + 3] + bv[j4 * 4 + 3];
            if (RELU) {
                o.x = fmaxf(o.x, 0.f); o.y = fmaxf(o.y, 0.f);
                o.z = fmaxf(o.z, 0.f); o.w = fmaxf(o.w, 0.f);
            }
            *(float4*)(C + r + j4 * 4) = o;
        }
    }
}

// ============================================================================
// Batched attention logits: out[bh, i, j] = (q_bh[i,:] . k_bh[j,:]) / 8 + mask[b,i,j]
// q,k: (B*S, D) row-major, head slice = cols [h*64, h*64+64).
// grid: (S/64, S/64, B*H), 256 threads, 64x64x16 tile, 4x4/thread.
// ============================================================================
__global__ __launch_bounds__(256) void attn_logits(
    const float* __restrict__ q, const float* __restrict__ k,
    const float* __restrict__ mask, float* __restrict__ out)
{
    const int bh = blockIdx.z;
    const int b = bh >> 4, h = bh & 15;
    const int row0 = blockIdx.y * 64, col0 = blockIdx.x * 64;
    const float* qb = q + (size_t)b * SS * DD + h * DH;
    const float* kb = k + (size_t)b * SS * DD + h * DH;
    const float* mb = mask + (size_t)b * SS * SS;
    float* ob = out + (size_t)bh * SS * SS;

    __shared__ float Qs[16][64];
    __shared__ float Ks[16][64];
    const int tid = threadIdx.x;
    const int tx = tid & 15, ty = tid >> 4;
    const int lrow = tid >> 2, lc4 = (tid & 3) * 4;

    float acc[4][4];
#pragma unroll
    for (int i = 0; i < 4; i++)
#pragma unroll
        for (int j = 0; j < 4; j++) acc[i][j] = 0.f;

#pragma unroll
    for (int k0 = 0; k0 < DH; k0 += 16) {
        float4 a = *(const float4*)(qb + (size_t)(row0 + lrow) * DD + k0 + lc4);
        Qs[lc4 + 0][lrow] = a.x; Qs[lc4 + 1][lrow] = a.y;
        Qs[lc4 + 2][lrow] = a.z; Qs[lc4 + 3][lrow] = a.w;
        float4 c = *(const float4*)(kb + (size_t)(col0 + lrow) * DD + k0 + lc4);
        Ks[lc4 + 0][lrow] = c.x; Ks[lc4 + 1][lrow] = c.y;
        Ks[lc4 + 2][lrow] = c.z; Ks[lc4 + 3][lrow] = c.w;
        __syncthreads();
#pragma unroll
        for (int kk = 0; kk < 16; kk++) {
            float ar[4], br[4];
#pragma unroll
            for (int i = 0; i < 4; i++) ar[i] = Qs[kk][ty * 4 + i];
#pragma unroll
            for (int j = 0; j < 4; j++) br[j] = Ks[kk][tx * 4 + j];
#pragma unroll
            for (int i = 0; i < 4; i++)
#pragma unroll
                for (int j = 0; j < 4; j++)
                    acc[i][j] = fmaf(ar[i], br[j], acc[i][j]);
        }
        __syncthreads();
    }

#pragma unroll
    for (int i = 0; i < 4; i++) {
        size_t r = (size_t)(row0 + ty * 4 + i) * SS + col0 + tx * 4;
        float4 m4 = *(const float4*)(mb + r);
        float4 o;
        o.x = acc[i][0] * 0.125f + m4.x;
        o.y = acc[i][1] * 0.125f + m4.y;
        o.z = acc[i][2] * 0.125f + m4.z;
        o.w = acc[i][3] * 0.125f + m4.w;
        *(float4*)(ob + r) = o;
    }
}

// ============================================================================
// In-place row softmax over rows of length 1024. One block per row.
// ============================================================================
__global__ __launch_bounds__(256) void softmax_rows(float* __restrict__ w)
{
    float* p = w + (size_t)blockIdx.x * SS;
    const int tid = threadIdx.x;
    float4 v = *(const float4*)(p + tid * 4);

    float m = fmaxf(fmaxf(v.x, v.y), fmaxf(v.z, v.w));
#pragma unroll
    for (int o = 16; o; o >>= 1) m = fmaxf(m, __shfl_xor_sync(0xffffffffu, m, o));
    __shared__ float smax[8];
    __shared__ float ssum[8];
    if ((tid & 31) == 0) smax[tid >> 5] = m;
    __syncthreads();
    float bm = smax[0];
#pragma unroll
    for (int i = 1; i < 8; i++) bm = fmaxf(bm, smax[i]);

    float e0 = expf(v.x - bm), e1 = expf(v.y - bm);
    float e2 = expf(v.z - bm), e3 = expf(v.w - bm);
    float s = e0 + e1 + e2 + e3;
#pragma unroll
    for (int o = 16; o; o >>= 1) s += __shfl_xor_sync(0xffffffffu, s, o);
    if ((tid & 31) == 0) ssum[tid >> 5] = s;
    __syncthreads();
    float tot = 0.f;
#pragma unroll
    for (int i = 0; i < 8; i++) tot += ssum[i];
    float inv = 1.f / tot;

    float4 o4;
    o4.x = e0 * inv; o4.y = e1 * inv; o4.z = e2 * inv; o4.w = e3 * inv;
    *(float4*)(p + tid * 4) = o4;
}

// ============================================================================
// Batched AV: ctx[b*S+i, h*64+n] = sum_j w[bh,i,j] * v[b*S+j, h*64+n]
// grid: (S/64, B*H), 64x64x16 tile, 4x4/thread.
// ============================================================================
__global__ __launch_bounds__(256) void attn_av(
    const float* __restrict__ w, const float* __restrict__ v,
    float* __restrict__ ctx)
{
    const int bh = blockIdx.y;
    const int b = bh >> 4, h = bh & 15;
    const int row0 = blockIdx.x * 64;
    const float* wb = w + (size_t)bh * SS * SS;
    const float* vb = v + (size_t)b * SS * DD + h * DH;

    __shared__ float Ws[16][64];
    __shared__ float Vs[16][64];
    const int tid = threadIdx.x;
    const int tx = tid & 15, ty = tid >> 4;
    const int lrow = tid >> 2, lc4 = (tid & 3) * 4;   // Ws: 64 rows x 16
    const int vr = tid >> 4,   vc4 = (tid & 15) * 4;  // Vs: 16 rows x 64

    float acc[4][4];
#pragma unroll
    for (int i = 0; i < 4; i++)
#pragma unroll
        for (int j = 0; j < 4; j++) acc[i][j] = 0.f;

    for (int k0 = 0; k0 < SS; k0 += 16) {
        float4 a = *(const float4*)(wb + (size_t)(row0 + lrow) * SS + k0 + lc4);
        Ws[lc4 + 0][lrow] = a.x; Ws[lc4 + 1][lrow] = a.y;
        Ws[lc4 + 2][lrow] = a.z; Ws[lc4 + 3][lrow] = a.w;
        float4 c = *(const float4*)(vb + (size_t)(k0 + vr) * DD + vc4);
        *(float4*)&Vs[vr][vc4] = c;
        __syncthreads();
#pragma unroll
        for (int kk = 0; kk < 16; kk++) {
            float ar[4], br[4];
#pragma unroll
            for (int i = 0; i < 4; i++) ar[i] = Ws[kk][ty * 4 + i];
#pragma unroll
            for (int j = 0; j < 4; j++) br[j] = Vs[kk][tx * 4 + j];
#pragma unroll
            for (int i = 0; i < 4; i++)
#pragma unroll
                for (int j = 0; j < 4; j++)
                    acc[i][j] = fmaf(ar[i], br[j], acc[i][j]);
        }
        __syncthreads();
    }

#pragma unroll
    for (int i = 0; i < 4; i++) {
        size_t r = (size_t)(b * SS + row0 + ty * 4 + i) * DD + h * DH + tx * 4;
        float4 o;
        o.x = acc[i][0]; o.y = acc[i][1]; o.z = acc[i][2]; o.w = acc[i][3];
        *(float4*)(ctx + r) = o;
    }
}

// ============================================================================
// Fused residual add + LayerNorm over rows of 1024. One block per row.
// out = LN(a + r) * g + beta
// ============================================================================
__global__ __launch_bounds__(256) void add_ln(
    const float* __restrict__ a, const float* __restrict__ r,
    const float* __restrict__ g, const float* __restrict__ beta,
    float* __restrict__ out)
{
    const size_t base = (size_t)blockIdx.x * DD;
    const int tid = threadIdx.x;
    float4 va = *(const float4*)(a + base + tid * 4);
    float4 vr = *(const float4*)(r + base + tid * 4);
    float x0 = va.x + vr.x, x1 = va.y + vr.y, x2 = va.z + vr.z, x3 = va.w + vr.w;

    float s = x0 + x1 + x2 + x3;
    float sq = x0 * x0 + x1 * x1 + x2 * x2 + x3 * x3;
#pragma unroll
    for (int o = 16; o; o >>= 1) {
        s  += __shfl_xor_sync(0xffffffffu, s, o);
        sq += __shfl_xor_sync(0xffffffffu, sq, o);
    }
    __shared__ float ss[8], ssq[8];
    if ((tid & 31) == 0) { ss[tid >> 5] = s; ssq[tid >> 5] = sq; }
    __syncthreads();
    float ts = 0.f, tsq = 0.f;
#pragma unroll
    for (int i = 0; i < 8; i++) { ts += ss[i]; tsq += ssq[i]; }
    const float mu = ts * (1.0f / DD);
    const float var = tsq * (1.0f / DD) - mu * mu;
    const float rs = rsqrtf(var + LN_EPS);

    float4 gg = *(const float4*)(g + tid * 4);
    float4 bb = *(const float4*)(beta + tid * 4);
    float4 o4;
    o4.x = (x0 - mu) * rs * gg.x + bb.x;
    o4.y = (x1 - mu) * rs * gg.y + bb.y;
    o4.z = (x2 - mu) * rs * gg.z + bb.z;
    o4.w = (x3 - mu) * rs * gg.w + bb.w;
    *(float4*)(out + base + tid * 4) = o4;
}

// ============================================================================
// Host launch
// ============================================================================
extern "C" void kernel_launch(void* const* d_in, const int* in_sizes, int n_in,
                              void* d_out, int out_size)
{
    (void)in_sizes; (void)n_in; (void)out_size;
    const float* x    = (const float*)d_in[0];
    const float* enc  = (const float*)d_in[1];
    const float* pad  = (const float*)d_in[2];   // dec_pad_mask  (MHA2)
    const float* sub  = (const float*)d_in[3];   // dec_subseq_mask (MHA1)
    const float* wq1w = (const float*)d_in[4];   const float* wq1b = (const float*)d_in[5];
    const float* wk1w = (const float*)d_in[6];   const float* wk1b = (const float*)d_in[7];
    const float* wv1w = (const float*)d_in[8];   const float* wv1b = (const float*)d_in[9];
    const float* wo1w = (const float*)d_in[10];  const float* wo1b = (const float*)d_in[11];
    const float* wq2w = (const float*)d_in[12];  const float* wq2b = (const float*)d_in[13];
    const float* wk2w = (const float*)d_in[14];  const float* wk2b = (const float*)d_in[15];
    const float* wv2w = (const float*)d_in[16];  const float* wv2b = (const float*)d_in[17];
    const float* wo2w = (const float*)d_in[18];  const float* wo2b = (const float*)d_in[19];
    const float* f1w  = (const float*)d_in[20];  const float* f1b  = (const float*)d_in[21];
    const float* f2w  = (const float*)d_in[22];  const float* f2b  = (const float*)d_in[23];
    const float* ln1g = (const float*)d_in[24];  const float* ln1b = (const float*)d_in[25];
    const float* ln2g = (const float*)d_in[26];  const float* ln2b = (const float*)d_in[27];
    const float* ln3g = (const float*)d_in[28];  const float* ln3b = (const float*)d_in[29];

    static float *q_p, *k_p, *v_p, *ctx_p, *mha_p, *res1_p, *res2_p, *ffn_p;
    static bool init = false;
    if (!init) {
        cudaGetSymbolAddress((void**)&q_p, g_q);
        cudaGetSymbolAddress((void**)&k_p, g_k);
        cudaGetSymbolAddress((void**)&v_p, g_v);
        cudaGetSymbolAddress((void**)&ctx_p, g_ctx);
        cudaGetSymbolAddress((void**)&mha_p, g_mha);
        cudaGetSymbolAddress((void**)&res1_p, g_res1);
        cudaGetSymbolAddress((void**)&res2_p, g_res2);
        cudaGetSymbolAddress((void**)&ffn_p, g_ffn);
        init = true;
    }

    // Output layout: out3 (B*S*D) | attn_w1 (B*H*S*S) | attn_w2 (B*H*S*S)
    float* out3 = (float*)d_out;
    float* aw1  = out3 + (size_t)MM * DD;
    float* aw2  = aw1 + (size_t)BB * HH * SS * SS;

    const dim3 gD(DD / 128, MM / 128);    // N=1024 GEMMs
    const dim3 gF(DFF / 128, MM / 128);   // N=4096 GEMM
    const dim3 gLog(SS / 64, SS / 64, BB * HH);
    const dim3 gAV(SS / 64, BB * HH);
    const int nRowsAttn = BB * HH * SS;   // 65536 softmax rows

    // ---- MHA1 (self-attention) ----
    sgemm_bias<false><<<gD, 256>>>(x, wq1w, wq1b, q_p, MM, DD, DD);
    sgemm_bias<false><<<gD, 256>>>(x, wk1w, wk1b, k_p, MM, DD, DD);
    sgemm_bias<false><<<gD, 256>>>(x, wv1w, wv1b, v_p, MM, DD, DD);
    attn_logits<<<gLog, 256>>>(q_p, k_p, sub, aw1);
    softmax_rows<<<nRowsAttn, 256>>>(aw1);
    attn_av<<<gAV, 256>>>(aw1, v_p, ctx_p);
    sgemm_bias<false><<<gD, 256>>>(ctx_p, wo1w, wo1b, mha_p, MM, DD, DD);
    add_ln<<<MM, 256>>>(mha_p, x, ln1g, ln1b, res1_p);

    // ---- MHA2 (cross-attention) ----
    sgemm_bias<false><<<gD, 256>>>(res1_p, wq2w, wq2b, q_p, MM, DD, DD);
    sgemm_bias<false><<<gD, 256>>>(enc, wk2w, wk2b, k_p, MM, DD, DD);
    sgemm_bias<false><<<gD, 256>>>(enc, wv2w, wv2b, v_p, MM, DD, DD);
    attn_logits<<<gLog, 256>>>(q_p, k_p, pad, aw2);
    softmax_rows<<<nRowsAttn, 256>>>(aw2);
    attn_av<<<gAV, 256>>>(aw2, v_p, ctx_p);
    sgemm_bias<false><<<gD, 256>>>(ctx_p, wo2w, wo2b, mha_p, MM, DD, DD);
    add_ln<<<MM, 256>>>(mha_p, res1_p, ln2g, ln2b, res2_p);

    // ---- FFN ----
    sgemm_bias<true ><<<gF, 256>>>(res2_p, f1w, f1b, ffn_p, MM, DFF, DD);
    sgemm_bias<false><<<gD, 256>>>(ffn_p, f2w, f2b, mha_p, MM, DD, DFF);
    add_ln<<<MM, 256>>>(mha_p, res2_p, ln3g, ln3b, out3);
}

// round 3
// speedup vs baseline: 1.9756x; 1.9756x over previous
#include <cuda_runtime.h>
#include <cstdint>
#include <math.h>

// Problem constants
#define BB   4
#define SS   1024
#define DD   1024
#define HH   16
#define DH   64
#define DFF  4096
#define MM   (BB*SS)          // 4096 rows
#define LN_EPS 1e-5f

// -------------------- scratch (static device globals; no runtime alloc) ----
__device__ float g_q[MM*DD];
__device__ float g_k[MM*DD];
__device__ float g_v[MM*DD];
__device__ float g_ctx[MM*DD];
__device__ float g_mha[MM*DD];
__device__ float g_res1[MM*DD];
__device__ float g_res2[MM*DD];
__device__ float g_ffn[(size_t)MM*DFF];

__device__ __forceinline__ uint32_t cvt_tf32(float f) {
    uint32_t r;
    asm("cvt.rna.tf32.f32 %0, %1;" : "=r"(r) : "f"(f));
    return r;
}

// ============================================================================
// tf32 mma.sync GEMM: C[M,N] = A[M,K] @ W[K,N] + bias, optional ReLU.
// CTA tile 128x128, BK=32, 256 threads = 8 warps (4x2), warp tile 32x64.
// As[128][36] (m-major), Bs[32][136] (k-major) -> conflict-free frag loads.
// Double-buffered SMEM + register-staged global prefetch.
// ============================================================================
#define AS_STR 36
#define BS_STR 136
#define A_FLTS (128*AS_STR)          // 4608
#define B_FLTS (32*BS_STR)           // 4352
#define BUF_FLTS (A_FLTS + B_FLTS)   // 8960
#define GEMM_SMEM_BYTES (2*BUF_FLTS*4)  // 71680

template<bool RELU>
__global__ void __launch_bounds__(256) gemm_mma(
    const float* __restrict__ A, const float* __restrict__ W,
    const float* __restrict__ bias, float* __restrict__ C,
    int M, int N, int K)
{
    extern __shared__ float sm[];
    const int tid = threadIdx.x;
    const int wid = tid >> 5, lane = tid & 31;
    const int g = lane >> 2, t = lane & 3;
    const int wm = (wid >> 1) * 32;   // warp row offset in tile
    const int wn = (wid & 1) * 64;    // warp col offset in tile
    const int row0 = blockIdx.y * 128, col0 = blockIdx.x * 128;

    // load mappings (4 iterations each, 1024 float4 per tile)
    int a_row[4], a_c4[4], b_k[4], b_n4[4];
#pragma unroll
    for (int it = 0; it < 4; it++) {
        int lin = it * 256 + tid;
        a_row[it] = lin >> 3;            // 0..127
        a_c4[it]  = (lin & 7) * 4;       // 0..28
        b_k[it]   = lin >> 5;            // 0..31
        b_n4[it]  = (lin & 31) * 4;      // 0..124
    }

    float acc[2][8][4];
#pragma unroll
    for (int mt = 0; mt < 2; mt++)
#pragma unroll
        for (int nt = 0; nt < 8; nt++)
#pragma unroll
            for (int i = 0; i < 4; i++) acc[mt][nt][i] = 0.f;

    const int nchunk = K >> 5;

    // ---- prologue: load chunk 0 into buffer 0 ----
    {
        float* sA = sm;
        float* sB = sm + A_FLTS;
#pragma unroll
        for (int it = 0; it < 4; it++) {
            float4 a = *(const float4*)(A + (size_t)(row0 + a_row[it]) * K + a_c4[it]);
            uint32_t* dA = (uint32_t*)(sA + a_row[it] * AS_STR + a_c4[it]);
            dA[0] = cvt_tf32(a.x); dA[1] = cvt_tf32(a.y);
            dA[2] = cvt_tf32(a.z); dA[3] = cvt_tf32(a.w);
            float4 b = *(const float4*)(W + (size_t)b_k[it] * N + col0 + b_n4[it]);
            uint32_t* dB = (uint32_t*)(sB + b_k[it] * BS_STR + b_n4[it]);
            dB[0] = cvt_tf32(b.x); dB[1] = cvt_tf32(b.y);
            dB[2] = cvt_tf32(b.z); dB[3] = cvt_tf32(b.w);
        }
    }
    __syncthreads();

    for (int ic = 0; ic < nchunk; ic++) {
        const int p = ic & 1;
        const bool has_next = (ic + 1 < nchunk);

        // prefetch next chunk into registers
        float4 pa[4], pb[4];
        if (has_next) {
            const int k1 = (ic + 1) << 5;
#pragma unroll
            for (int it = 0; it < 4; it++) {
                pa[it] = *(const float4*)(A + (size_t)(row0 + a_row[it]) * K + k1 + a_c4[it]);
                pb[it] = *(const float4*)(W + (size_t)(k1 + b_k[it]) * N + col0 + b_n4[it]);
            }
        }

        // compute on buffer p
        const float* sA = sm + (p ? BUF_FLTS : 0);
        const float* sB = sA + A_FLTS;
#pragma unroll
        for (int ks = 0; ks < 4; ks++) {
            const int k8 = ks * 8;
            uint32_t af[2][4];
#pragma unroll
            for (int mt = 0; mt < 2; mt++) {
                const int r = wm + mt * 16 + g;
                af[mt][0] = __float_as_uint(sA[r * AS_STR + k8 + t]);
                af[mt][1] = __float_as_uint(sA[(r + 8) * AS_STR + k8 + t]);
                af[mt][2] = __float_as_uint(sA[r * AS_STR + k8 + 4 + t]);
                af[mt][3] = __float_as_uint(sA[(r + 8) * AS_STR + k8 + 4 + t]);
            }
            uint32_t bf[8][2];
#pragma unroll
            for (int nt = 0; nt < 8; nt++) {
                const int n = wn + nt * 8 + g;
                bf[nt][0] = __float_as_uint(sB[(k8 + t) * BS_STR + n]);
                bf[nt][1] = __float_as_uint(sB[(k8 + 4 + t) * BS_STR + n]);
            }
#pragma unroll
            for (int mt = 0; mt < 2; mt++)
#pragma unroll
                for (int nt = 0; nt < 8; nt++)
                    asm volatile(
                        "mma.sync.aligned.m16n8k8.row.col.f32.tf32.tf32.f32 "
                        "{%0,%1,%2,%3}, {%4,%5,%6,%7}, {%8,%9}, {%0,%1,%2,%3};"
                        : "+f"(acc[mt][nt][0]), "+f"(acc[mt][nt][1]),
                          "+f"(acc[mt][nt][2]), "+f"(acc[mt][nt][3])
                        : "r"(af[mt][0]), "r"(af[mt][1]), "r"(af[mt][2]), "r"(af[mt][3]),
                          "r"(bf[nt][0]), "r"(bf[nt][1]));
        }

        // store prefetched chunk into the other buffer
        if (has_next) {
            float* nA = sm + (p ? 0 : BUF_FLTS);
            float* nB = nA + A_FLTS;
#pragma unroll
            for (int it = 0; it < 4; it++) {
                uint32_t* dA = (uint32_t*)(nA + a_row[it] * AS_STR + a_c4[it]);
                dA[0] = cvt_tf32(pa[it].x); dA[1] = cvt_tf32(pa[it].y);
                dA[2] = cvt_tf32(pa[it].z); dA[3] = cvt_tf32(pa[it].w);
                uint32_t* dB = (uint32_t*)(nB + b_k[it] * BS_STR + b_n4[it]);
                dB[0] = cvt_tf32(pb[it].x); dB[1] = cvt_tf32(pb[it].y);
                dB[2] = cvt_tf32(pb[it].z); dB[3] = cvt_tf32(pb[it].w);
            }
            __syncthreads();
        }
    }

    // ---- epilogue: bias (+ReLU), fp32 stores ----
#pragma unroll
    for (int mt = 0; mt < 2; mt++) {
        const int ra = row0 + wm + mt * 16 + g;
#pragma unroll
        for (int nt = 0; nt < 8; nt++) {
            const int cc = col0 + wn + nt * 8 + 2 * t;
            float2 bv = *(const float2*)(bias + cc);
            float v0 = acc[mt][nt][0] + bv.x;
            float v1 = acc[mt][nt][1] + bv.y;
            float v2 = acc[mt][nt][2] + bv.x;
            float v3 = acc[mt][nt][3] + bv.y;
            if (RELU) {
                v0 = fmaxf(v0, 0.f); v1 = fmaxf(v1, 0.f);
                v2 = fmaxf(v2, 0.f); v3 = fmaxf(v3, 0.f);
            }
            float2 o01 = make_float2(v0, v1);
            float2 o23 = make_float2(v2, v3);
            *(float2*)(C + (size_t)ra * N + cc) = o01;
            *(float2*)(C + (size_t)(ra + 8) * N + cc) = o23;
        }
    }
}

// ============================================================================
// Batched attention logits (fp32 SIMT)
// ============================================================================
__global__ __launch_bounds__(256) void attn_logits(
    const float* __restrict__ q, const float* __restrict__ k,
    const float* __restrict__ mask, float* __restrict__ out)
{
    const int bh = blockIdx.z;
    const int b = bh >> 4, h = bh & 15;
    const int row0 = blockIdx.y * 64, col0 = blockIdx.x * 64;
    const float* qb = q + (size_t)b * SS * DD + h * DH;
    const float* kb = k + (size_t)b * SS * DD + h * DH;
    const float* mb = mask + (size_t)b * SS * SS;
    float* ob = out + (size_t)bh * SS * SS;

    __shared__ float Qs[16][64];
    __shared__ float Ks[16][64];
    const int tid = threadIdx.x;
    const int tx = tid & 15, ty = tid >> 4;
    const int lrow = tid >> 2, lc4 = (tid & 3) * 4;

    float acc[4][4];
#pragma unroll
    for (int i = 0; i < 4; i++)
#pragma unroll
        for (int j = 0; j < 4; j++) acc[i][j] = 0.f;

#pragma unroll
    for (int k0 = 0; k0 < DH; k0 += 16) {
        float4 a = *(const float4*)(qb + (size_t)(row0 + lrow) * DD + k0 + lc4);
        Qs[lc4 + 0][lrow] = a.x; Qs[lc4 + 1][lrow] = a.y;
        Qs[lc4 + 2][lrow] = a.z; Qs[lc4 + 3][lrow] = a.w;
        float4 c = *(const float4*)(kb + (size_t)(col0 + lrow) * DD + k0 + lc4);
        Ks[lc4 + 0][lrow] = c.x; Ks[lc4 + 1][lrow] = c.y;
        Ks[lc4 + 2][lrow] = c.z; Ks[lc4 + 3][lrow] = c.w;
        __syncthreads();
#pragma unroll
        for (int kk = 0; kk < 16; kk++) {
            float ar[4], br[4];
#pragma unroll
            for (int i = 0; i < 4; i++) ar[i] = Qs[kk][ty * 4 + i];
#pragma unroll
            for (int j = 0; j < 4; j++) br[j] = Ks[kk][tx * 4 + j];
#pragma unroll
            for (int i = 0; i < 4; i++)
#pragma unroll
                for (int j = 0; j < 4; j++)
                    acc[i][j] = fmaf(ar[i], br[j], acc[i][j]);
        }
        __syncthreads();
    }

#pragma unroll
    for (int i = 0; i < 4; i++) {
        size_t r = (size_t)(row0 + ty * 4 + i) * SS + col0 + tx * 4;
        float4 m4 = *(const float4*)(mb + r);
        float4 o;
        o.x = acc[i][0] * 0.125f + m4.x;
        o.y = acc[i][1] * 0.125f + m4.y;
        o.z = acc[i][2] * 0.125f + m4.z;
        o.w = acc[i][3] * 0.125f + m4.w;
        *(float4*)(ob + r) = o;
    }
}

// ============================================================================
// In-place row softmax over rows of length 1024.
// ============================================================================
__global__ __launch_bounds__(256) void softmax_rows(float* __restrict__ w)
{
    float* p = w + (size_t)blockIdx.x * SS;
    const int tid = threadIdx.x;
    float4 v = *(const float4*)(p + tid * 4);

    float m = fmaxf(fmaxf(v.x, v.y), fmaxf(v.z, v.w));
#pragma unroll
    for (int o = 16; o; o >>= 1) m = fmaxf(m, __shfl_xor_sync(0xffffffffu, m, o));
    __shared__ float smax[8];
    __shared__ float ssum[8];
    if ((tid & 31) == 0) smax[tid >> 5] = m;
    __syncthreads();
    float bm = smax[0];
#pragma unroll
    for (int i = 1; i < 8; i++) bm = fmaxf(bm, smax[i]);

    float e0 = expf(v.x - bm), e1 = expf(v.y - bm);
    float e2 = expf(v.z - bm), e3 = expf(v.w - bm);
    float s = e0 + e1 + e2 + e3;
#pragma unroll
    for (int o = 16; o; o >>= 1) s += __shfl_xor_sync(0xffffffffu, s, o);
    if ((tid & 31) == 0) ssum[tid >> 5] = s;
    __syncthreads();
    float tot = 0.f;
#pragma unroll
    for (int i = 0; i < 8; i++) tot += ssum[i];
    float inv = 1.f / tot;

    float4 o4;
    o4.x = e0 * inv; o4.y = e1 * inv; o4.z = e2 * inv; o4.w = e3 * inv;
    *(float4*)(p + tid * 4) = o4;
}

// ============================================================================
// Batched AV (fp32 SIMT)
// ============================================================================
__global__ __launch_bounds__(256) void attn_av(
    const float* __restrict__ w, const float* __restrict__ v,
    float* __restrict__ ctx)
{
    const int bh = blockIdx.y;
    const int b = bh >> 4, h = bh & 15;
    const int row0 = blockIdx.x * 64;
    const float* wb = w + (size_t)bh * SS * SS;
    const float* vb = v + (size_t)b * SS * DD + h * DH;

    __shared__ float Ws[16][64];
    __shared__ float Vs[16][64];
    const int tid = threadIdx.x;
    const int tx = tid & 15, ty = tid >> 4;
    const int lrow = tid >> 2, lc4 = (tid & 3) * 4;
    const int vr = tid >> 4,   vc4 = (tid & 15) * 4;

    float acc[4][4];
#pragma unroll
    for (int i = 0; i < 4; i++)
#pragma unroll
        for (int j = 0; j < 4; j++) acc[i][j] = 0.f;

    for (int k0 = 0; k0 < SS; k0 += 16) {
        float4 a = *(const float4*)(wb + (size_t)(row0 + lrow) * SS + k0 + lc4);
        Ws[lc4 + 0][lrow] = a.x; Ws[lc4 + 1][lrow] = a.y;
        Ws[lc4 + 2][lrow] = a.z; Ws[lc4 + 3][lrow] = a.w;
        float4 c = *(const float4*)(vb + (size_t)(k0 + vr) * DD + vc4);
        *(float4*)&Vs[vr][vc4] = c;
        __syncthreads();
#pragma unroll
        for (int kk = 0; kk < 16; kk++) {
            float ar[4], br[4];
#pragma unroll
            for (int i = 0; i < 4; i++) ar[i] = Ws[kk][ty * 4 + i];
#pragma unroll
            for (int j = 0; j < 4; j++) br[j] = Vs[kk][tx * 4 + j];
#pragma unroll
            for (int i = 0; i < 4; i++)
#pragma unroll
                for (int j = 0; j < 4; j++)
                    acc[i][j] = fmaf(ar[i], br[j], acc[i][j]);
        }
        __syncthreads();
    }

#pragma unroll
    for (int i = 0; i < 4; i++) {
        size_t r = (size_t)(b * SS + row0 + ty * 4 + i) * DD + h * DH + tx * 4;
        float4 o;
        o.x = acc[i][0]; o.y = acc[i][1]; o.z = acc[i][2]; o.w = acc[i][3];
        *(float4*)(ctx + r) = o;
    }
}

// ============================================================================
// Fused residual add + LayerNorm
// ============================================================================
__global__ __launch_bounds__(256) void add_ln(
    const float* __restrict__ a, const float* __restrict__ r,
    const float* __restrict__ g, const float* __restrict__ beta,
    float* __restrict__ out)
{
    const size_t base = (size_t)blockIdx.x * DD;
    const int tid = threadIdx.x;
    float4 va = *(const float4*)(a + base + tid * 4);
    float4 vr = *(const float4*)(r + base + tid * 4);
    float x0 = va.x + vr.x, x1 = va.y + vr.y, x2 = va.z + vr.z, x3 = va.w + vr.w;

    float s = x0 + x1 + x2 + x3;
    float sq = x0 * x0 + x1 * x1 + x2 * x2 + x3 * x3;
#pragma unroll
    for (int o = 16; o; o >>= 1) {
        s  += __shfl_xor_sync(0xffffffffu, s, o);
        sq += __shfl_xor_sync(0xffffffffu, sq, o);
    }
    __shared__ float ss[8], ssq[8];
    if ((tid & 31) == 0) { ss[tid >> 5] = s; ssq[tid >> 5] = sq; }
    __syncthreads();
    float ts = 0.f, tsq = 0.f;
#pragma unroll
    for (int i = 0; i < 8; i++) { ts += ss[i]; tsq += ssq[i]; }
    const float mu = ts * (1.0f / DD);
    const float var = tsq * (1.0f / DD) - mu * mu;
    const float rs = rsqrtf(var + LN_EPS);

    float4 gg = *(const float4*)(g + tid * 4);
    float4 bb = *(const float4*)(beta + tid * 4);
    float4 o4;
    o4.x = (x0 - mu) * rs * gg.x + bb.x;
    o4.y = (x1 - mu) * rs * gg.y + bb.y;
    o4.z = (x2 - mu) * rs * gg.z + bb.z;
    o4.w = (x3 - mu) * rs * gg.w + bb.w;
    *(float4*)(out + base + tid * 4) = o4;
}

// ============================================================================
// Host launch
// ============================================================================
extern "C" void kernel_launch(void* const* d_in, const int* in_sizes, int n_in,
                              void* d_out, int out_size)
{
    (void)in_sizes; (void)n_in; (void)out_size;
    const float* x    = (const float*)d_in[0];
    const float* enc  = (const float*)d_in[1];
    const float* pad  = (const float*)d_in[2];
    const float* sub  = (const float*)d_in[3];
    const float* wq1w = (const float*)d_in[4];   const float* wq1b = (const float*)d_in[5];
    const float* wk1w = (const float*)d_in[6];   const float* wk1b = (const float*)d_in[7];
    const float* wv1w = (const float*)d_in[8];   const float* wv1b = (const float*)d_in[9];
    const float* wo1w = (const float*)d_in[10];  const float* wo1b = (const float*)d_in[11];
    const float* wq2w = (const float*)d_in[12];  const float* wq2b = (const float*)d_in[13];
    const float* wk2w = (const float*)d_in[14];  const float* wk2b = (const float*)d_in[15];
    const float* wv2w = (const float*)d_in[16];  const float* wv2b = (const float*)d_in[17];
    const float* wo2w = (const float*)d_in[18];  const float* wo2b = (const float*)d_in[19];
    const float* f1w  = (const float*)d_in[20];  const float* f1b  = (const float*)d_in[21];
    const float* f2w  = (const float*)d_in[22];  const float* f2b  = (const float*)d_in[23];
    const float* ln1g = (const float*)d_in[24];  const float* ln1b = (const float*)d_in[25];
    const float* ln2g = (const float*)d_in[26];  const float* ln2b = (const float*)d_in[27];
    const float* ln3g = (const float*)d_in[28];  const float* ln3b = (const float*)d_in[29];

    static float *q_p, *k_p, *v_p, *ctx_p, *mha_p, *res1_p, *res2_p, *ffn_p;
    static bool init = false;
    if (!init) {
        cudaGetSymbolAddress((void**)&q_p, g_q);
        cudaGetSymbolAddress((void**)&k_p, g_k);
        cudaGetSymbolAddress((void**)&v_p, g_v);
        cudaGetSymbolAddress((void**)&ctx_p, g_ctx);
        cudaGetSymbolAddress((void**)&mha_p, g_mha);
        cudaGetSymbolAddress((void**)&res1_p, g_res1);
        cudaGetSymbolAddress((void**)&res2_p, g_res2);
        cudaGetSymbolAddress((void**)&ffn_p, g_ffn);
        cudaFuncSetAttribute(gemm_mma<false>,
            cudaFuncAttributeMaxDynamicSharedMemorySize, GEMM_SMEM_BYTES);
        cudaFuncSetAttribute(gemm_mma<true>,
            cudaFuncAttributeMaxDynamicSharedMemorySize, GEMM_SMEM_BYTES);
        init = true;
    }

    // Output layout: out3 | attn_w1 | attn_w2
    float* out3 = (float*)d_out;
    float* aw1  = out3 + (size_t)MM * DD;
    float* aw2  = aw1 + (size_t)BB * HH * SS * SS;

    const dim3 gD(DD / 128, MM / 128);
    const dim3 gF(DFF / 128, MM / 128);
    const dim3 gLog(SS / 64, SS / 64, BB * HH);
    const dim3 gAV(SS / 64, BB * HH);
    const int nRowsAttn = BB * HH * SS;

    // ---- MHA1 (self-attention) ----
    gemm_mma<false><<<gD, 256, GEMM_SMEM_BYTES>>>(x, wq1w, wq1b, q_p, MM, DD, DD);
    gemm_mma<false><<<gD, 256, GEMM_SMEM_BYTES>>>(x, wk1w, wk1b, k_p, MM, DD, DD);
    gemm_mma<false><<<gD, 256, GEMM_SMEM_BYTES>>>(x, wv1w, wv1b, v_p, MM, DD, DD);
    attn_logits<<<gLog, 256>>>(q_p, k_p, sub, aw1);
    softmax_rows<<<nRowsAttn, 256>>>(aw1);
    attn_av<<<gAV, 256>>>(aw1, v_p, ctx_p);
    gemm_mma<false><<<gD, 256, GEMM_SMEM_BYTES>>>(ctx_p, wo1w, wo1b, mha_p, MM, DD, DD);
    add_ln<<<MM, 256>>>(mha_p, x, ln1g, ln1b, res1_p);

    // ---- MHA2 (cross-attention) ----
    gemm_mma<false><<<gD, 256, GEMM_SMEM_BYTES>>>(res1_p, wq2w, wq2b, q_p, MM, DD, DD);
    gemm_mma<false><<<gD, 256, GEMM_SMEM_BYTES>>>(enc, wk2w, wk2b, k_p, MM, DD, DD);
    gemm_mma<false><<<gD, 256, GEMM_SMEM_BYTES>>>(enc, wv2w, wv2b, v_p, MM, DD, DD);
    attn_logits<<<gLog, 256>>>(q_p, k_p, pad, aw2);
    softmax_rows<<<nRowsAttn, 256>>>(aw2);
    attn_av<<<gAV, 256>>>(aw2, v_p, ctx_p);
    gemm_mma<false><<<gD, 256, GEMM_SMEM_BYTES>>>(ctx_p, wo2w, wo2b, mha_p, MM, DD, DD);
    add_ln<<<MM, 256>>>(mha_p, res1_p, ln2g, ln2b, res2_p);

    // ---- FFN ----
    gemm_mma<true ><<<gF, 256, GEMM_SMEM_BYTES>>>(res2_p, f1w, f1b, ffn_p, MM, DFF, DD);
    gemm_mma<false><<<gD, 256, GEMM_SMEM_BYTES>>>(ffn_p, f2w, f2b, mha_p, MM, DD, DFF);
    add_ln<<<MM, 256>>>(mha_p, res2_p, ln3g, ln3b, out3);
}

// round 5
// speedup vs baseline: 2.3376x; 1.1832x over previous
#include <cuda_runtime.h>
#include <cstdint>
#include <math.h>

// Problem constants
#define BB   4
#define SS   1024
#define DD   1024
#define HH   16
#define DH   64
#define DFF  4096
#define MM   (BB*SS)          // 4096 rows
#define LN_EPS 1e-5f

// -------------------- scratch (static device globals; no runtime alloc) ----
__device__ float g_q[MM*DD];
__device__ float g_k[MM*DD];
__device__ float g_v[MM*DD];
__device__ float g_ctx[MM*DD];
__device__ float g_mha[MM*DD];
__device__ float g_res1[MM*DD];
__device__ float g_res2[MM*DD];
__device__ float g_ffn[(size_t)MM*DFF];

__device__ __forceinline__ uint32_t cvt_tf32(float f) {
    uint32_t r;
    asm("cvt.rna.tf32.f32 %0, %1;" : "=r"(r) : "f"(f));
    return r;
}

__device__ __forceinline__ void mma_tf32(float* c,
    uint32_t a0, uint32_t a1, uint32_t a2, uint32_t a3,
    uint32_t b0, uint32_t b1)
{
    asm volatile(
        "mma.sync.aligned.m16n8k8.row.col.f32.tf32.tf32.f32 "
        "{%0,%1,%2,%3}, {%4,%5,%6,%7}, {%8,%9}, {%0,%1,%2,%3};"
        : "+f"(c[0]), "+f"(c[1]), "+f"(c[2]), "+f"(c[3])
        : "r"(a0), "r"(a1), "r"(a2), "r"(a3), "r"(b0), "r"(b1));
}

// ============================================================================
// tf32 mma.sync GEMM: C[M,N] = A[M,K] @ W[K,N] + bias, optional ReLU.
// CTA tile 128x128, BK=32, 256 threads = 8 warps (4x2), warp tile 32x64.
// ============================================================================
#define AS_STR 36
#define BS_STR 136
#define A_FLTS (128*AS_STR)          // 4608
#define B_FLTS (32*BS_STR)           // 4352
#define BUF_FLTS (A_FLTS + B_FLTS)   // 8960
#define GEMM_SMEM_BYTES (2*BUF_FLTS*4)  // 71680

template<bool RELU>
__global__ void __launch_bounds__(256) gemm_mma(
    const float* __restrict__ A, const float* __restrict__ W,
    const float* __restrict__ bias, float* __restrict__ C,
    int M, int N, int K)
{
    extern __shared__ float sm[];
    const int tid = threadIdx.x;
    const int wid = tid >> 5, lane = tid & 31;
    const int g = lane >> 2, t = lane & 3;
    const int wm = (wid >> 1) * 32;
    const int wn = (wid & 1) * 64;
    const int row0 = blockIdx.y * 128, col0 = blockIdx.x * 128;

    int a_row[4], a_c4[4], b_k[4], b_n4[4];
#pragma unroll
    for (int it = 0; it < 4; it++) {
        int lin = it * 256 + tid;
        a_row[it] = lin >> 3;
        a_c4[it]  = (lin & 7) * 4;
        b_k[it]   = lin >> 5;
        b_n4[it]  = (lin & 31) * 4;
    }

    float acc[2][8][4];
#pragma unroll
    for (int mt = 0; mt < 2; mt++)
#pragma unroll
        for (int nt = 0; nt < 8; nt++)
#pragma unroll
            for (int i = 0; i < 4; i++) acc[mt][nt][i] = 0.f;

    const int nchunk = K >> 5;

    {
        float* sA = sm;
        float* sB = sm + A_FLTS;
#pragma unroll
        for (int it = 0; it < 4; it++) {
            float4 a = *(const float4*)(A + (size_t)(row0 + a_row[it]) * K + a_c4[it]);
            uint32_t* dA = (uint32_t*)(sA + a_row[it] * AS_STR + a_c4[it]);
            dA[0] = cvt_tf32(a.x); dA[1] = cvt_tf32(a.y);
            dA[2] = cvt_tf32(a.z); dA[3] = cvt_tf32(a.w);
            float4 b = *(const float4*)(W + (size_t)b_k[it] * N + col0 + b_n4[it]);
            uint32_t* dB = (uint32_t*)(sB + b_k[it] * BS_STR + b_n4[it]);
            dB[0] = cvt_tf32(b.x); dB[1] = cvt_tf32(b.y);
            dB[2] = cvt_tf32(b.z); dB[3] = cvt_tf32(b.w);
        }
    }
    __syncthreads();

    for (int ic = 0; ic < nchunk; ic++) {
        const int p = ic & 1;
        const bool has_next = (ic + 1 < nchunk);

        float4 pa[4], pb[4];
        if (has_next) {
            const int k1 = (ic + 1) << 5;
#pragma unroll
            for (int it = 0; it < 4; it++) {
                pa[it] = *(const float4*)(A + (size_t)(row0 + a_row[it]) * K + k1 + a_c4[it]);
                pb[it] = *(const float4*)(W + (size_t)(k1 + b_k[it]) * N + col0 + b_n4[it]);
            }
        }

        const float* sA = sm + (p ? BUF_FLTS : 0);
        const float* sB = sA + A_FLTS;
#pragma unroll
        for (int ks = 0; ks < 4; ks++) {
            const int k8 = ks * 8;
            uint32_t af[2][4];
#pragma unroll
            for (int mt = 0; mt < 2; mt++) {
                const int r = wm + mt * 16 + g;
                af[mt][0] = __float_as_uint(sA[r * AS_STR + k8 + t]);
                af[mt][1] = __float_as_uint(sA[(r + 8) * AS_STR + k8 + t]);
                af[mt][2] = __float_as_uint(sA[r * AS_STR + k8 + 4 + t]);
                af[mt][3] = __float_as_uint(sA[(r + 8) * AS_STR + k8 + 4 + t]);
            }
            uint32_t bf[8][2];
#pragma unroll
            for (int nt = 0; nt < 8; nt++) {
                const int n = wn + nt * 8 + g;
                bf[nt][0] = __float_as_uint(sB[(k8 + t) * BS_STR + n]);
                bf[nt][1] = __float_as_uint(sB[(k8 + 4 + t) * BS_STR + n]);
            }
#pragma unroll
            for (int mt = 0; mt < 2; mt++)
#pragma unroll
                for (int nt = 0; nt < 8; nt++)
                    mma_tf32(acc[mt][nt], af[mt][0], af[mt][1], af[mt][2], af[mt][3],
                             bf[nt][0], bf[nt][1]);
        }

        if (has_next) {
            float* nA = sm + (p ? 0 : BUF_FLTS);
            float* nB = nA + A_FLTS;
#pragma unroll
            for (int it = 0; it < 4; it++) {
                uint32_t* dA = (uint32_t*)(nA + a_row[it] * AS_STR + a_c4[it]);
                dA[0] = cvt_tf32(pa[it].x); dA[1] = cvt_tf32(pa[it].y);
                dA[2] = cvt_tf32(pa[it].z); dA[3] = cvt_tf32(pa[it].w);
                uint32_t* dB = (uint32_t*)(nB + b_k[it] * BS_STR + b_n4[it]);
                dB[0] = cvt_tf32(pb[it].x); dB[1] = cvt_tf32(pb[it].y);
                dB[2] = cvt_tf32(pb[it].z); dB[3] = cvt_tf32(pb[it].w);
            }
            __syncthreads();
        }
    }

#pragma unroll
    for (int mt = 0; mt < 2; mt++) {
        const int ra = row0 + wm + mt * 16 + g;
#pragma unroll
        for (int nt = 0; nt < 8; nt++) {
            const int cc = col0 + wn + nt * 8 + 2 * t;
            float2 bv = *(const float2*)(bias + cc);
            float v0 = acc[mt][nt][0] + bv.x;
            float v1 = acc[mt][nt][1] + bv.y;
            float v2 = acc[mt][nt][2] + bv.x;
            float v3 = acc[mt][nt][3] + bv.y;
            if (RELU) {
                v0 = fmaxf(v0, 0.f); v1 = fmaxf(v1, 0.f);
                v2 = fmaxf(v2, 0.f); v3 = fmaxf(v3, 0.f);
            }
            *(float2*)(C + (size_t)ra * N + cc) = make_float2(v0, v1);
            *(float2*)(C + (size_t)(ra + 8) * N + cc) = make_float2(v2, v3);
        }
    }
}

// ============================================================================
// Attention logits via 3xTF32 mma: out = QK^T/8 + mask.
// CTA 128x128 per (bh), K=64 one shot. 8 warps (4x2), warp tile 32x64.
// ============================================================================
#define LQ_STR 68
#define LK_STR 136
#define LOG_SMEM_BYTES ((2*128*LQ_STR + 2*64*LK_STR)*4)   // 139264

__global__ void __launch_bounds__(256) attn_logits_mma(
    const float* __restrict__ q, const float* __restrict__ k,
    const float* __restrict__ mask, float* __restrict__ out)
{
    extern __shared__ float sm[];
    float* Qhi = sm;
    float* Qlo = Qhi + 128 * LQ_STR;
    float* Khi = Qlo + 128 * LQ_STR;
    float* Klo = Khi + 64 * LK_STR;

    const int tid = threadIdx.x;
    const int wid = tid >> 5, lane = tid & 31;
    const int g = lane >> 2, t = lane & 3;
    const int wm = (wid >> 1) * 32;
    const int wn = (wid & 1) * 64;

    const int bh = blockIdx.z;
    const int b = bh >> 4, h = bh & 15;
    const int row0 = blockIdx.y * 128, col0 = blockIdx.x * 128;
    const float* qb = q + (size_t)b * SS * DD + h * DH;
    const float* kb = k + (size_t)b * SS * DD + h * DH;

    // load Q tile [128][64], split hi/lo
#pragma unroll
    for (int it = 0; it < 8; it++) {
        const int lin = it * 256 + tid;
        const int r = lin >> 4, c4 = (lin & 15) * 4;
        float4 v = *(const float4*)(qb + (size_t)(row0 + r) * DD + c4);
        float vv[4] = {v.x, v.y, v.z, v.w};
#pragma unroll
        for (int j = 0; j < 4; j++) {
            uint32_t hi = cvt_tf32(vv[j]);
            uint32_t lo = cvt_tf32(vv[j] - __uint_as_float(hi));
            Qhi[r * LQ_STR + c4 + j] = __uint_as_float(hi);
            Qlo[r * LQ_STR + c4 + j] = __uint_as_float(lo);
        }
    }
    // load K tile transposed: Ks[k][n] = K[col0+n][k], split hi/lo
#pragma unroll
    for (int it = 0; it < 4; it++) {
        const int lin = it * 256 + tid;
        const int n = lin & 127, k8g = (lin >> 7) * 8;
        const float* src = kb + (size_t)(col0 + n) * DD + k8g;
        float4 v0 = *(const float4*)(src);
        float4 v1 = *(const float4*)(src + 4);
        float vv[8] = {v0.x, v0.y, v0.z, v0.w, v1.x, v1.y, v1.z, v1.w};
#pragma unroll
        for (int j = 0; j < 8; j++) {
            uint32_t hi = cvt_tf32(vv[j]);
            uint32_t lo = cvt_tf32(vv[j] - __uint_as_float(hi));
            Khi[(k8g + j) * LK_STR + n] = __uint_as_float(hi);
            Klo[(k8g + j) * LK_STR + n] = __uint_as_float(lo);
        }
    }
    __syncthreads();

    float acc[2][8][4];
#pragma unroll
    for (int mt = 0; mt < 2; mt++)
#pragma unroll
        for (int nt = 0; nt < 8; nt++)
#pragma unroll
            for (int i = 0; i < 4; i++) acc[mt][nt][i] = 0.f;

#pragma unroll
    for (int ks = 0; ks < 8; ks++) {
        const int k8 = ks * 8;
        uint32_t ah[2][4], al[2][4];
#pragma unroll
        for (int mt = 0; mt < 2; mt++) {
            const int r = wm + mt * 16 + g;
            ah[mt][0] = __float_as_uint(Qhi[r * LQ_STR + k8 + t]);
            ah[mt][1] = __float_as_uint(Qhi[(r + 8) * LQ_STR + k8 + t]);
            ah[mt][2] = __float_as_uint(Qhi[r * LQ_STR + k8 + 4 + t]);
            ah[mt][3] = __float_as_uint(Qhi[(r + 8) * LQ_STR + k8 + 4 + t]);
            al[mt][0] = __float_as_uint(Qlo[r * LQ_STR + k8 + t]);
            al[mt][1] = __float_as_uint(Qlo[(r + 8) * LQ_STR + k8 + t]);
            al[mt][2] = __float_as_uint(Qlo[r * LQ_STR + k8 + 4 + t]);
            al[mt][3] = __float_as_uint(Qlo[(r + 8) * LQ_STR + k8 + 4 + t]);
        }
#pragma unroll
        for (int nt = 0; nt < 8; nt++) {
            const int n = wn + nt * 8 + g;
            uint32_t bh0 = __float_as_uint(Khi[(k8 + t) * LK_STR + n]);
            uint32_t bh1 = __float_as_uint(Khi[(k8 + 4 + t) * LK_STR + n]);
            uint32_t bl0 = __float_as_uint(Klo[(k8 + t) * LK_STR + n]);
            uint32_t bl1 = __float_as_uint(Klo[(k8 + 4 + t) * LK_STR + n]);
#pragma unroll
            for (int mt = 0; mt < 2; mt++) {
                mma_tf32(acc[mt][nt], ah[mt][0], ah[mt][1], ah[mt][2], ah[mt][3], bl0, bl1);
                mma_tf32(acc[mt][nt], al[mt][0], al[mt][1], al[mt][2], al[mt][3], bh0, bh1);
                mma_tf32(acc[mt][nt], ah[mt][0], ah[mt][1], ah[mt][2], ah[mt][3], bh0, bh1);
            }
        }
    }

    const float* mb = mask + (size_t)b * SS * SS;
    float* ob = out + (size_t)bh * SS * SS;
#pragma unroll
    for (int mt = 0; mt < 2; mt++) {
        const int r = row0 + wm + mt * 16 + g;
#pragma unroll
        for (int nt = 0; nt < 8; nt++) {
            const int c = col0 + wn + nt * 8 + 2 * t;
            float2 m0 = *(const float2*)(mb + (size_t)r * SS + c);
            float2 m1 = *(const float2*)(mb + (size_t)(r + 8) * SS + c);
            *(float2*)(ob + (size_t)r * SS + c) =
                make_float2(acc[mt][nt][0] * 0.125f + m0.x,
                            acc[mt][nt][1] * 0.125f + m0.y);
            *(float2*)(ob + (size_t)(r + 8) * SS + c) =
                make_float2(acc[mt][nt][2] * 0.125f + m1.x,
                            acc[mt][nt][3] * 0.125f + m1.y);
        }
    }
}

// ============================================================================
// Batched AV via tf32 mma: ctx[row, h*64+n] = sum_k w[bh,row,k] * v[k, h*64+n]
// CTA 128x64, K=1024 in 32 chunks, double-buffered. 8 warps (4x2), warp 32x32.
// B tile: 32 (k) x 64 (n), stride 72 -> bank = 8t+g, conflict-free.
// ============================================================================
#define AVA_STR 36
#define AVB_STR 72
#define AV_A_FLTS (128*AVA_STR)          // 4608
#define AV_B_FLTS (32*AVB_STR)           // 2304
#define AV_BUF (AV_A_FLTS + AV_B_FLTS)   // 6912
#define AV_SMEM_BYTES (2*AV_BUF*4)       // 55296

__global__ void __launch_bounds__(256) attn_av_mma(
    const float* __restrict__ w, const float* __restrict__ v,
    float* __restrict__ ctx)
{
    extern __shared__ float sm[];
    const int tid = threadIdx.x;
    const int wid = tid >> 5, lane = tid & 31;
    const int g = lane >> 2, t = lane & 3;
    const int wm = (wid >> 1) * 32;
    const int wn = (wid & 1) * 32;

    const int bh = blockIdx.y;
    const int b = bh >> 4, h = bh & 15;
    const int row0 = blockIdx.x * 128;
    const float* wb = w + (size_t)bh * SS * SS;
    const float* vb = v + (size_t)b * SS * DD + h * DH;

    int a_row[4], a_c4[4], b_k[2], b_n4[2];
#pragma unroll
    for (int it = 0; it < 4; it++) {
        int lin = it * 256 + tid;
        a_row[it] = lin >> 3;
        a_c4[it]  = (lin & 7) * 4;
    }
#pragma unroll
    for (int it = 0; it < 2; it++) {
        int lin = it * 256 + tid;
        b_k[it]  = lin >> 4;
        b_n4[it] = (lin & 15) * 4;
    }

    float acc[2][4][4];
#pragma unroll
    for (int mt = 0; mt < 2; mt++)
#pragma unroll
        for (int nt = 0; nt < 4; nt++)
#pragma unroll
            for (int i = 0; i < 4; i++) acc[mt][nt][i] = 0.f;

    {
        float* sA = sm;
        float* sB = sm + AV_A_FLTS;
#pragma unroll
        for (int it = 0; it < 4; it++) {
            float4 a = *(const float4*)(wb + (size_t)(row0 + a_row[it]) * SS + a_c4[it]);
            uint32_t* dA = (uint32_t*)(sA + a_row[it] * AVA_STR + a_c4[it]);
            dA[0] = cvt_tf32(a.x); dA[1] = cvt_tf32(a.y);
            dA[2] = cvt_tf32(a.z); dA[3] = cvt_tf32(a.w);
        }
#pragma unroll
        for (int it = 0; it < 2; it++) {
            float4 bv = *(const float4*)(vb + (size_t)b_k[it] * DD + b_n4[it]);
            uint32_t* dB = (uint32_t*)(sB + b_k[it] * AVB_STR + b_n4[it]);
            dB[0] = cvt_tf32(bv.x); dB[1] = cvt_tf32(bv.y);
            dB[2] = cvt_tf32(bv.z); dB[3] = cvt_tf32(bv.w);
        }
    }
    __syncthreads();

    for (int ic = 0; ic < 32; ic++) {
        const int p = ic & 1;
        const bool has_next = (ic + 1 < 32);

        float4 pa[4], pb[2];
        if (has_next) {
            const int k1 = (ic + 1) << 5;
#pragma unroll
            for (int it = 0; it < 4; it++)
                pa[it] = *(const float4*)(wb + (size_t)(row0 + a_row[it]) * SS + k1 + a_c4[it]);
#pragma unroll
            for (int it = 0; it < 2; it++)
                pb[it] = *(const float4*)(vb + (size_t)(k1 + b_k[it]) * DD + b_n4[it]);
        }

        const float* sA = sm + (p ? AV_BUF : 0);
        const float* sB = sA + AV_A_FLTS;
#pragma unroll
        for (int ks = 0; ks < 4; ks++) {
            const int k8 = ks * 8;
            uint32_t af[2][4];
#pragma unroll
            for (int mt = 0; mt < 2; mt++) {
                const int r = wm + mt * 16 + g;
                af[mt][0] = __float_as_uint(sA[r * AVA_STR + k8 + t]);
                af[mt][1] = __float_as_uint(sA[(r + 8) * AVA_STR + k8 + t]);
                af[mt][2] = __float_as_uint(sA[r * AVA_STR + k8 + 4 + t]);
                af[mt][3] = __float_as_uint(sA[(r + 8) * AVA_STR + k8 + 4 + t]);
            }
            uint32_t bf[4][2];
#pragma unroll
            for (int nt = 0; nt < 4; nt++) {
                const int n = wn + nt * 8 + g;
                bf[nt][0] = __float_as_uint(sB[(k8 + t) * AVB_STR + n]);
                bf[nt][1] = __float_as_uint(sB[(k8 + 4 + t) * AVB_STR + n]);
            }
#pragma unroll
            for (int mt = 0; mt < 2; mt++)
#pragma unroll
                for (int nt = 0; nt < 4; nt++)
                    mma_tf32(acc[mt][nt], af[mt][0], af[mt][1], af[mt][2], af[mt][3],
                             bf[nt][0], bf[nt][1]);
        }

        if (has_next) {
            float* nA = sm + (p ? 0 : AV_BUF);
            float* nB = nA + AV_A_FLTS;
#pragma unroll
            for (int it = 0; it < 4; it++) {
                uint32_t* dA = (uint32_t*)(nA + a_row[it] * AVA_STR + a_c4[it]);
                dA[0] = cvt_tf32(pa[it].x); dA[1] = cvt_tf32(pa[it].y);
                dA[2] = cvt_tf32(pa[it].z); dA[3] = cvt_tf32(pa[it].w);
            }
#pragma unroll
            for (int it = 0; it < 2; it++) {
                uint32_t* dB = (uint32_t*)(nB + b_k[it] * AVB_STR + b_n4[it]);
                dB[0] = cvt_tf32(pb[it].x); dB[1] = cvt_tf32(pb[it].y);
                dB[2] = cvt_tf32(pb[it].z); dB[3] = cvt_tf32(pb[it].w);
            }
            __syncthreads();
        }
    }

#pragma unroll
    for (int mt = 0; mt < 2; mt++) {
        const int ra = row0 + wm + mt * 16 + g;
#pragma unroll
        for (int nt = 0; nt < 4; nt++) {
            const int cc = wn + nt * 8 + 2 * t;
            float* dst0 = ctx + (size_t)(b * SS + ra) * DD + h * DH + cc;
            float* dst1 = ctx + (size_t)(b * SS + ra + 8) * DD + h * DH + cc;
            *(float2*)dst0 = make_float2(acc[mt][nt][0], acc[mt][nt][1]);
            *(float2*)dst1 = make_float2(acc[mt][nt][2], acc[mt][nt][3]);
        }
    }
}

// ============================================================================
// In-place row softmax over rows of length 1024.
// ============================================================================
__global__ __launch_bounds__(256) void softmax_rows(float* __restrict__ w)
{
    float* p = w + (size_t)blockIdx.x * SS;
    const int tid = threadIdx.x;
    float4 v = *(const float4*)(p + tid * 4);

    float m = fmaxf(fmaxf(v.x, v.y), fmaxf(v.z, v.w));
#pragma unroll
    for (int o = 16; o; o >>= 1) m = fmaxf(m, __shfl_xor_sync(0xffffffffu, m, o));
    __shared__ float smax[8];
    __shared__ float ssum[8];
    if ((tid & 31) == 0) smax[tid >> 5] = m;
    __syncthreads();
    float bm = smax[0];
#pragma unroll
    for (int i = 1; i < 8; i++) bm = fmaxf(bm, smax[i]);

    float e0 = expf(v.x - bm), e1 = expf(v.y - bm);
    float e2 = expf(v.z - bm), e3 = expf(v.w - bm);
    float s = e0 + e1 + e2 + e3;
#pragma unroll
    for (int o = 16; o; o >>= 1) s += __shfl_xor_sync(0xffffffffu, s, o);
    if ((tid & 31) == 0) ssum[tid >> 5] = s;
    __syncthreads();
    float tot = 0.f;
#pragma unroll
    for (int i = 0; i < 8; i++) tot += ssum[i];
    float inv = 1.f / tot;

    float4 o4;
    o4.x = e0 * inv; o4.y = e1 * inv; o4.z = e2 * inv; o4.w = e3 * inv;
    *(float4*)(p + tid * 4) = o4;
}

// ============================================================================
// Fused residual add + LayerNorm
// ============================================================================
__global__ __launch_bounds__(256) void add_ln(
    const float* __restrict__ a, const float* __restrict__ r,
    const float* __restrict__ g, const float* __restrict__ beta,
    float* __restrict__ out)
{
    const size_t base = (size_t)blockIdx.x * DD;
    const int tid = threadIdx.x;
    float4 va = *(const float4*)(a + base + tid * 4);
    float4 vr = *(const float4*)(r + base + tid * 4);
    float x0 = va.x + vr.x, x1 = va.y + vr.y, x2 = va.z + vr.z, x3 = va.w + vr.w;

    float s = x0 + x1 + x2 + x3;
    float sq = x0 * x0 + x1 * x1 + x2 * x2 + x3 * x3;
#pragma unroll
    for (int o = 16; o; o >>= 1) {
        s  += __shfl_xor_sync(0xffffffffu, s, o);
        sq += __shfl_xor_sync(0xffffffffu, sq, o);
    }
    __shared__ float ss[8], ssq[8];
    if ((tid & 31) == 0) { ss[tid >> 5] = s; ssq[tid >> 5] = sq; }
    __syncthreads();
    float ts = 0.f, tsq = 0.f;
#pragma unroll
    for (int i = 0; i < 8; i++) { ts += ss[i]; tsq += ssq[i]; }
    const float mu = ts * (1.0f / DD);
    const float var = tsq * (1.0f / DD) - mu * mu;
    const float rs = rsqrtf(var + LN_EPS);

    float4 gg = *(const float4*)(g + tid * 4);
    float4 bb = *(const float4*)(beta + tid * 4);
    float4 o4;
    o4.x = (x0 - mu) * rs * gg.x + bb.x;
    o4.y = (x1 - mu) * rs * gg.y + bb.y;
    o4.z = (x2 - mu) * rs * gg.z + bb.z;
    o4.w = (x3 - mu) * rs * gg.w + bb.w;
    *(float4*)(out + base + tid * 4) = o4;
}

// ============================================================================
// Host launch
// ============================================================================
extern "C" void kernel_launch(void* const* d_in, const int* in_sizes, int n_in,
                              void* d_out, int out_size)
{
    (void)in_sizes; (void)n_in; (void)out_size;
    const float* x    = (const float*)d_in[0];
    const float* enc  = (const float*)d_in[1];
    const float* pad  = (const float*)d_in[2];
    const float* sub  = (const float*)d_in[3];
    const float* wq1w = (const float*)d_in[4];   const float* wq1b = (const float*)d_in[5];
    const float* wk1w = (const float*)d_in[6];   const float* wk1b = (const float*)d_in[7];
    const float* wv1w = (const float*)d_in[8];   const float* wv1b = (const float*)d_in[9];
    const float* wo1w = (const float*)d_in[10];  const float* wo1b = (const float*)d_in[11];
    const float* wq2w = (const float*)d_in[12];  const float* wq2b = (const float*)d_in[13];
    const float* wk2w = (const float*)d_in[14];  const float* wk2b = (const float*)d_in[15];
    const float* wv2w = (const float*)d_in[16];  const float* wv2b = (const float*)d_in[17];
    const float* wo2w = (const float*)d_in[18];  const float* wo2b = (const float*)d_in[19];
    const float* f1w  = (const float*)d_in[20];  const float* f1b  = (const float*)d_in[21];
    const float* f2w  = (const float*)d_in[22];  const float* f2b  = (const float*)d_in[23];
    const float* ln1g = (const float*)d_in[24];  const float* ln1b = (const float*)d_in[25];
    const float* ln2g = (const float*)d_in[26];  const float* ln2b = (const float*)d_in[27];
    const float* ln3g = (const float*)d_in[28];  const float* ln3b = (const float*)d_in[29];

    static float *q_p, *k_p, *v_p, *ctx_p, *mha_p, *res1_p, *res2_p, *ffn_p;
    static bool init = false;
    if (!init) {
        cudaGetSymbolAddress((void**)&q_p, g_q);
        cudaGetSymbolAddress((void**)&k_p, g_k);
        cudaGetSymbolAddress((void**)&v_p, g_v);
        cudaGetSymbolAddress((void**)&ctx_p, g_ctx);
        cudaGetSymbolAddress((void**)&mha_p, g_mha);
        cudaGetSymbolAddress((void**)&res1_p, g_res1);
        cudaGetSymbolAddress((void**)&res2_p, g_res2);
        cudaGetSymbolAddress((void**)&ffn_p, g_ffn);
        cudaFuncSetAttribute(gemm_mma<false>,
            cudaFuncAttributeMaxDynamicSharedMemorySize, GEMM_SMEM_BYTES);
        cudaFuncSetAttribute(gemm_mma<true>,
            cudaFuncAttributeMaxDynamicSharedMemorySize, GEMM_SMEM_BYTES);
        cudaFuncSetAttribute(attn_logits_mma,
            cudaFuncAttributeMaxDynamicSharedMemorySize, LOG_SMEM_BYTES);
        cudaFuncSetAttribute(attn_av_mma,
            cudaFuncAttributeMaxDynamicSharedMemorySize, AV_SMEM_BYTES);
        init = true;
    }

    // Output layout: out3 | attn_w1 | attn_w2
    float* out3 = (float*)d_out;
    float* aw1  = out3 + (size_t)MM * DD;
    float* aw2  = aw1 + (size_t)BB * HH * SS * SS;

    const dim3 gD(DD / 128, MM / 128);
    const dim3 gF(DFF / 128, MM / 128);
    const dim3 gLog(SS / 128, SS / 128, BB * HH);
    const dim3 gAV(SS / 128, BB * HH);
    const int nRowsAttn = BB * HH * SS;

    // ---- MHA1 (self-attention) ----
    gemm_mma<false><<<gD, 256, GEMM_SMEM_BYTES>>>(x, wq1w, wq1b, q_p, MM, DD, DD);
    gemm_mma<false><<<gD, 256, GEMM_SMEM_BYTES>>>(x, wk1w, wk1b, k_p, MM, DD, DD);
    gemm_mma<false><<<gD, 256, GEMM_SMEM_BYTES>>>(x, wv1w, wv1b, v_p, MM, DD, DD);
    attn_logits_mma<<<gLog, 256, LOG_SMEM_BYTES>>>(q_p, k_p, sub, aw1);
    softmax_rows<<<nRowsAttn, 256>>>(aw1);
    attn_av_mma<<<gAV, 256, AV_SMEM_BYTES>>>(aw1, v_p, ctx_p);
    gemm_mma<false><<<gD, 256, GEMM_SMEM_BYTES>>>(ctx_p, wo1w, wo1b, mha_p, MM, DD, DD);
    add_ln<<<MM, 256>>>(mha_p, x, ln1g, ln1b, res1_p);

    // ---- MHA2 (cross-attention) ----
    gemm_mma<false><<<gD, 256, GEMM_SMEM_BYTES>>>(res1_p, wq2w, wq2b, q_p, MM, DD, DD);
    gemm_mma<false><<<gD, 256, GEMM_SMEM_BYTES>>>(enc, wk2w, wk2b, k_p, MM, DD, DD);
    gemm_mma<false><<<gD, 256, GEMM_SMEM_BYTES>>>(enc, wv2w, wv2b, v_p, MM, DD, DD);
    attn_logits_mma<<<gLog, 256, LOG_SMEM_BYTES>>>(q_p, k_p, pad, aw2);
    softmax_rows<<<nRowsAttn, 256>>>(aw2);
    attn_av_mma<<<gAV, 256, AV_SMEM_BYTES>>>(aw2, v_p, ctx_p);
    gemm_mma<false><<<gD, 256, GEMM_SMEM_BYTES>>>(ctx_p, wo2w, wo2b, mha_p, MM, DD, DD);
    add_ln<<<MM, 256>>>(mha_p, res1_p, ln2g, ln2b, res2_p);

    // ---- FFN ----
    gemm_mma<true ><<<gF, 256, GEMM_SMEM_BYTES>>>(res2_p, f1w, f1b, ffn_p, MM, DFF, DD);
    gemm_mma<false><<<gD, 256, GEMM_SMEM_BYTES>>>(ffn_p, f2w, f2b, mha_p, MM, DD, DFF);
    add_ln<<<MM, 256>>>(mha_p, res2_p, ln3g, ln3b, out3);
}

// round 6
// speedup vs baseline: 2.9138x; 1.2465x over previous
#include <cuda_runtime.h>
#include <cstdint>
#include <math.h>

// Problem constants
#define BB   4
#define SS   1024
#define DD   1024
#define HH   16
#define DH   64
#define DFF  4096
#define MM   (BB*SS)          // 4096 rows
#define LN_EPS 1e-5f

// -------------------- scratch (static device globals; no runtime alloc) ----
__device__ float g_q[MM*DD];
__device__ float g_k[MM*DD];
__device__ float g_v[MM*DD];
__device__ float g_ctx[MM*DD];
__device__ float g_mha[MM*DD];
__device__ float g_res1[MM*DD];
__device__ float g_res2[MM*DD];
__device__ float g_ffn[(size_t)MM*DFF];
__device__ float g_wt[16u*1024u*1024u];   // tf32-rounded weights (concatenated)
__device__ float g_xr[MM*DD];
__device__ float g_encr[MM*DD];
__device__ float g_res1r[MM*DD];
__device__ float g_res2r[MM*DD];

__device__ __forceinline__ uint32_t cvt_tf32(float f) {
    uint32_t r;
    asm("cvt.rna.tf32.f32 %0, %1;" : "=r"(r) : "f"(f));
    return r;
}
__device__ __forceinline__ float rnd_tf32(float f) {
    return __uint_as_float(cvt_tf32(f));
}
__device__ __forceinline__ uint32_t smem_u32(const void* p) {
    uint32_t a;
    asm("{ .reg .u64 t; cvta.to.shared.u64 t, %1; cvt.u32.u64 %0, t; }"
        : "=r"(a) : "l"(p));
    return a;
}
__device__ __forceinline__ void cp16(uint32_t dst, const void* src) {
    asm volatile("cp.async.ca.shared.global [%0], [%1], 16;" :: "r"(dst), "l"(src));
}
#define CP_COMMIT() asm volatile("cp.async.commit_group;")
#define CP_WAIT0()  asm volatile("cp.async.wait_group 0;")
#define CP_WAIT1()  asm volatile("cp.async.wait_group 1;")

__device__ __forceinline__ void mma_tf32(float* c,
    uint32_t a0, uint32_t a1, uint32_t a2, uint32_t a3,
    uint32_t b0, uint32_t b1)
{
    asm volatile(
        "mma.sync.aligned.m16n8k8.row.col.f32.tf32.tf32.f32 "
        "{%0,%1,%2,%3}, {%4,%5,%6,%7}, {%8,%9}, {%0,%1,%2,%3};"
        : "+f"(c[0]), "+f"(c[1]), "+f"(c[2]), "+f"(c[3])
        : "r"(a0), "r"(a1), "r"(a2), "r"(a3), "r"(b0), "r"(b1));
}

// ============================================================================
// Elementwise tf32 rounding (float4): out[i] = rna_tf32(in[i])
// ============================================================================
__global__ __launch_bounds__(256) void round_tf32_k(
    const float4* __restrict__ in, float4* __restrict__ out)
{
    int i = blockIdx.x * 256 + threadIdx.x;
    float4 v = in[i];
    float4 o;
    o.x = rnd_tf32(v.x); o.y = rnd_tf32(v.y);
    o.z = rnd_tf32(v.z); o.w = rnd_tf32(v.w);
    out[i] = o;
}

// ============================================================================
// tf32 mma GEMM w/ cp.async: C = A@W + bias. Inputs pre-rounded to tf32.
// CTA 128x128, BK=32, 256 thr = 8 warps (4x2), warp tile 32x64, double-buffer.
// ============================================================================
#define AS_STR 36
#define BS_STR 136
#define A_FLTS (128*AS_STR)
#define B_FLTS (32*BS_STR)
#define BUF_FLTS (A_FLTS + B_FLTS)       // 8960
#define GEMM_SMEM_BYTES (2*BUF_FLTS*4)   // 71680

template<bool RELU, bool ROUND>
__global__ void __launch_bounds__(256, 2) gemm_ca(
    const float* __restrict__ A, const float* __restrict__ W,
    const float* __restrict__ bias, float* __restrict__ C,
    int M, int N, int K)
{
    extern __shared__ float sm[];
    const uint32_t smb = smem_u32(sm);
    const int tid = threadIdx.x;
    const int wid = tid >> 5, lane = tid & 31;
    const int g = lane >> 2, t = lane & 3;
    const int wm = (wid >> 1) * 32;
    const int wn = (wid & 1) * 64;
    const int row0 = blockIdx.y * 128, col0 = blockIdx.x * 128;

    int a_row[4], a_c4[4], b_k[4], b_n4[4];
#pragma unroll
    for (int it = 0; it < 4; it++) {
        int lin = it * 256 + tid;
        a_row[it] = lin >> 3;
        a_c4[it]  = (lin & 7) * 4;
        b_k[it]   = lin >> 5;
        b_n4[it]  = (lin & 31) * 4;
    }

    float acc[2][8][4];
#pragma unroll
    for (int mt = 0; mt < 2; mt++)
#pragma unroll
        for (int nt = 0; nt < 8; nt++)
#pragma unroll
            for (int i = 0; i < 4; i++) acc[mt][nt][i] = 0.f;

    const int nchunk = K >> 5;

    // prologue: fill buffer 0
    {
        const uint32_t ab = smb, bb = smb + A_FLTS * 4;
#pragma unroll
        for (int it = 0; it < 4; it++) {
            cp16(ab + (a_row[it] * AS_STR + a_c4[it]) * 4,
                 A + (size_t)(row0 + a_row[it]) * K + a_c4[it]);
            cp16(bb + (b_k[it] * BS_STR + b_n4[it]) * 4,
                 W + (size_t)b_k[it] * N + col0 + b_n4[it]);
        }
        CP_COMMIT();
    }

    for (int ic = 0; ic < nchunk; ic++) {
        const int p = ic & 1;
        const bool has_next = (ic + 1 < nchunk);
        if (has_next) {
            const int k1 = (ic + 1) << 5;
            const uint32_t ab = smb + (p ? 0 : BUF_FLTS * 4);
            const uint32_t bb = ab + A_FLTS * 4;
#pragma unroll
            for (int it = 0; it < 4; it++) {
                cp16(ab + (a_row[it] * AS_STR + a_c4[it]) * 4,
                     A + (size_t)(row0 + a_row[it]) * K + k1 + a_c4[it]);
                cp16(bb + (b_k[it] * BS_STR + b_n4[it]) * 4,
                     W + (size_t)(k1 + b_k[it]) * N + col0 + b_n4[it]);
            }
            CP_COMMIT();
            CP_WAIT1();
        } else {
            CP_WAIT0();
        }
        __syncthreads();

        const float* sA = sm + (p ? BUF_FLTS : 0);
        const float* sB = sA + A_FLTS;
#pragma unroll
        for (int ks = 0; ks < 4; ks++) {
            const int k8 = ks * 8;
            uint32_t af[2][4];
#pragma unroll
            for (int mt = 0; mt < 2; mt++) {
                const int r = wm + mt * 16 + g;
                af[mt][0] = __float_as_uint(sA[r * AS_STR + k8 + t]);
                af[mt][1] = __float_as_uint(sA[(r + 8) * AS_STR + k8 + t]);
                af[mt][2] = __float_as_uint(sA[r * AS_STR + k8 + 4 + t]);
                af[mt][3] = __float_as_uint(sA[(r + 8) * AS_STR + k8 + 4 + t]);
            }
            uint32_t bf[8][2];
#pragma unroll
            for (int nt = 0; nt < 8; nt++) {
                const int n = wn + nt * 8 + g;
                bf[nt][0] = __float_as_uint(sB[(k8 + t) * BS_STR + n]);
                bf[nt][1] = __float_as_uint(sB[(k8 + 4 + t) * BS_STR + n]);
            }
#pragma unroll
            for (int mt = 0; mt < 2; mt++)
#pragma unroll
                for (int nt = 0; nt < 8; nt++)
                    mma_tf32(acc[mt][nt], af[mt][0], af[mt][1], af[mt][2], af[mt][3],
                             bf[nt][0], bf[nt][1]);
        }
        __syncthreads();
    }

#pragma unroll
    for (int mt = 0; mt < 2; mt++) {
        const int ra = row0 + wm + mt * 16 + g;
#pragma unroll
        for (int nt = 0; nt < 8; nt++) {
            const int cc = col0 + wn + nt * 8 + 2 * t;
            float2 bv = *(const float2*)(bias + cc);
            float v0 = acc[mt][nt][0] + bv.x;
            float v1 = acc[mt][nt][1] + bv.y;
            float v2 = acc[mt][nt][2] + bv.x;
            float v3 = acc[mt][nt][3] + bv.y;
            if (RELU) {
                v0 = fmaxf(v0, 0.f); v1 = fmaxf(v1, 0.f);
                v2 = fmaxf(v2, 0.f); v3 = fmaxf(v3, 0.f);
            }
            if (ROUND) {
                v0 = rnd_tf32(v0); v1 = rnd_tf32(v1);
                v2 = rnd_tf32(v2); v3 = rnd_tf32(v3);
            }
            *(float2*)(C + (size_t)ra * N + cc) = make_float2(v0, v1);
            *(float2*)(C + (size_t)(ra + 8) * N + cc) = make_float2(v2, v3);
        }
    }
}

// ============================================================================
// Attention logits: out = QK^T/8 + mask. Q split hi/lo (exact), K plain tf32
// (pre-rounded, cp.async'd raw in [n][k] layout). 2 MMAs per fragment pair.
// CTA 128x128 per (bh), K=64 one shot. SMEM 104.4KB -> 2 CTAs/SM.
// ============================================================================
#define L2_STR 68
#define LOG_SMEM_BYTES (3*128*L2_STR*4)   // 104448

__global__ void __launch_bounds__(256, 2) attn_logits2(
    const float* __restrict__ q, const float* __restrict__ k,
    const float* __restrict__ mask, float* __restrict__ out)
{
    extern __shared__ float sm[];
    float* Qhi = sm;
    float* Qlo = Qhi + 128 * L2_STR;
    float* Ks  = Qlo + 128 * L2_STR;
    const uint32_t ks_u32 = smem_u32(Ks);

    const int tid = threadIdx.x;
    const int wid = tid >> 5, lane = tid & 31;
    const int g = lane >> 2, t = lane & 3;
    const int wm = (wid >> 1) * 32;
    const int wn = (wid & 1) * 64;

    const int bh = blockIdx.z;
    const int b = bh >> 4, h = bh & 15;
    const int row0 = blockIdx.y * 128, col0 = blockIdx.x * 128;
    const float* qb = q + (size_t)b * SS * DD + h * DH;
    const float* kb = k + (size_t)b * SS * DD + h * DH;

    // K tile [n][k] raw via cp.async (values already tf32-rounded)
#pragma unroll
    for (int it = 0; it < 8; it++) {
        const int lin = it * 256 + tid;
        const int n = lin >> 4, c4 = (lin & 15) * 4;
        cp16(ks_u32 + (n * L2_STR + c4) * 4,
             kb + (size_t)(col0 + n) * DD + c4);
    }
    CP_COMMIT();

    // Q tile [m][k], split hi/lo (exact reconstruction of fp32 q)
#pragma unroll
    for (int it = 0; it < 8; it++) {
        const int lin = it * 256 + tid;
        const int r = lin >> 4, c4 = (lin & 15) * 4;
        float4 v = *(const float4*)(qb + (size_t)(row0 + r) * DD + c4);
        float vv[4] = {v.x, v.y, v.z, v.w};
#pragma unroll
        for (int j = 0; j < 4; j++) {
            float hi = rnd_tf32(vv[j]);
            Qhi[r * L2_STR + c4 + j] = hi;
            Qlo[r * L2_STR + c4 + j] = rnd_tf32(vv[j] - hi);
        }
    }
    CP_WAIT0();
    __syncthreads();

    float acc[2][8][4];
#pragma unroll
    for (int mt = 0; mt < 2; mt++)
#pragma unroll
        for (int nt = 0; nt < 8; nt++)
#pragma unroll
            for (int i = 0; i < 4; i++) acc[mt][nt][i] = 0.f;

#pragma unroll
    for (int ks = 0; ks < 8; ks++) {
        const int k8 = ks * 8;
        uint32_t ah[2][4], al[2][4];
#pragma unroll
        for (int mt = 0; mt < 2; mt++) {
            const int r = wm + mt * 16 + g;
            ah[mt][0] = __float_as_uint(Qhi[r * L2_STR + k8 + t]);
            ah[mt][1] = __float_as_uint(Qhi[(r + 8) * L2_STR + k8 + t]);
            ah[mt][2] = __float_as_uint(Qhi[r * L2_STR + k8 + 4 + t]);
            ah[mt][3] = __float_as_uint(Qhi[(r + 8) * L2_STR + k8 + 4 + t]);
            al[mt][0] = __float_as_uint(Qlo[r * L2_STR + k8 + t]);
            al[mt][1] = __float_as_uint(Qlo[(r + 8) * L2_STR + k8 + t]);
            al[mt][2] = __float_as_uint(Qlo[r * L2_STR + k8 + 4 + t]);
            al[mt][3] = __float_as_uint(Qlo[(r + 8) * L2_STR + k8 + 4 + t]);
        }
#pragma unroll
        for (int nt = 0; nt < 8; nt++) {
            const int n = wn + nt * 8 + g;
            uint32_t b0 = __float_as_uint(Ks[n * L2_STR + k8 + t]);
            uint32_t b1 = __float_as_uint(Ks[n * L2_STR + k8 + 4 + t]);
#pragma unroll
            for (int mt = 0; mt < 2; mt++) {
                mma_tf32(acc[mt][nt], al[mt][0], al[mt][1], al[mt][2], al[mt][3], b0, b1);
                mma_tf32(acc[mt][nt], ah[mt][0], ah[mt][1], ah[mt][2], ah[mt][3], b0, b1);
            }
        }
    }

    const float* mb = mask + (size_t)b * SS * SS;
    float* ob = out + (size_t)bh * SS * SS;
#pragma unroll
    for (int mt = 0; mt < 2; mt++) {
        const int r = row0 + wm + mt * 16 + g;
#pragma unroll
        for (int nt = 0; nt < 8; nt++) {
            const int c = col0 + wn + nt * 8 + 2 * t;
            float2 m0 = *(const float2*)(mb + (size_t)r * SS + c);
            float2 m1 = *(const float2*)(mb + (size_t)(r + 8) * SS + c);
            *(float2*)(ob + (size_t)r * SS + c) =
                make_float2(acc[mt][nt][0] * 0.125f + m0.x,
                            acc[mt][nt][1] * 0.125f + m0.y);
            *(float2*)(ob + (size_t)(r + 8) * SS + c) =
                make_float2(acc[mt][nt][2] * 0.125f + m1.x,
                            acc[mt][nt][3] * 0.125f + m1.y);
        }
    }
}

// ============================================================================
// Batched AV w/ cp.async: both inputs pre-rounded. Epilogue rounds ctx.
// CTA 128x64, K=1024/32 chunks, double-buffered. 8 warps, warp 32x32.
// ============================================================================
#define AVA_STR 36
#define AVB_STR 72
#define AV_A_FLTS (128*AVA_STR)
#define AV_B_FLTS (32*AVB_STR)
#define AV_BUF (AV_A_FLTS + AV_B_FLTS)   // 6912
#define AV_SMEM_BYTES (2*AV_BUF*4)       // 55296

__global__ void __launch_bounds__(256, 2) attn_av_ca(
    const float* __restrict__ w, const float* __restrict__ v,
    float* __restrict__ ctx)
{
    extern __shared__ float sm[];
    const uint32_t smb = smem_u32(sm);
    const int tid = threadIdx.x;
    const int wid = tid >> 5, lane = tid & 31;
    const int g = lane >> 2, t = lane & 3;
    const int wm = (wid >> 1) * 32;
    const int wn = (wid & 1) * 32;

    const int bh = blockIdx.y;
    const int b = bh >> 4, h = bh & 15;
    const int row0 = blockIdx.x * 128;
    const float* wb = w + (size_t)bh * SS * SS;
    const float* vb = v + (size_t)b * SS * DD + h * DH;

    int a_row[4], a_c4[4], b_k[2], b_n4[2];
#pragma unroll
    for (int it = 0; it < 4; it++) {
        int lin = it * 256 + tid;
        a_row[it] = lin >> 3;
        a_c4[it]  = (lin & 7) * 4;
    }
#pragma unroll
    for (int it = 0; it < 2; it++) {
        int lin = it * 256 + tid;
        b_k[it]  = lin >> 4;
        b_n4[it] = (lin & 15) * 4;
    }

    float acc[2][4][4];
#pragma unroll
    for (int mt = 0; mt < 2; mt++)
#pragma unroll
        for (int nt = 0; nt < 4; nt++)
#pragma unroll
            for (int i = 0; i < 4; i++) acc[mt][nt][i] = 0.f;

    {
        const uint32_t ab = smb, bb = smb + AV_A_FLTS * 4;
#pragma unroll
        for (int it = 0; it < 4; it++)
            cp16(ab + (a_row[it] * AVA_STR + a_c4[it]) * 4,
                 wb + (size_t)(row0 + a_row[it]) * SS + a_c4[it]);
#pragma unroll
        for (int it = 0; it < 2; it++)
            cp16(bb + (b_k[it] * AVB_STR + b_n4[it]) * 4,
                 vb + (size_t)b_k[it] * DD + b_n4[it]);
        CP_COMMIT();
    }

    for (int ic = 0; ic < 32; ic++) {
        const int p = ic & 1;
        const bool has_next = (ic + 1 < 32);
        if (has_next) {
            const int k1 = (ic + 1) << 5;
            const uint32_t ab = smb + (p ? 0 : AV_BUF * 4);
            const uint32_t bb = ab + AV_A_FLTS * 4;
#pragma unroll
            for (int it = 0; it < 4; it++)
                cp16(ab + (a_row[it] * AVA_STR + a_c4[it]) * 4,
                     wb + (size_t)(row0 + a_row[it]) * SS + k1 + a_c4[it]);
#pragma unroll
            for (int it = 0; it < 2; it++)
                cp16(bb + (b_k[it] * AVB_STR + b_n4[it]) * 4,
                     vb + (size_t)(k1 + b_k[it]) * DD + b_n4[it]);
            CP_COMMIT();
            CP_WAIT1();
        } else {
            CP_WAIT0();
        }
        __syncthreads();

        const float* sA = sm + (p ? AV_BUF : 0);
        const float* sB = sA + AV_A_FLTS;
#pragma unroll
        for (int ks = 0; ks < 4; ks++) {
            const int k8 = ks * 8;
            uint32_t af[2][4];
#pragma unroll
            for (int mt = 0; mt < 2; mt++) {
                const int r = wm + mt * 16 + g;
                af[mt][0] = __float_as_uint(sA[r * AVA_STR + k8 + t]);
                af[mt][1] = __float_as_uint(sA[(r + 8) * AVA_STR + k8 + t]);
                af[mt][2] = __float_as_uint(sA[r * AVA_STR + k8 + 4 + t]);
                af[mt][3] = __float_as_uint(sA[(r + 8) * AVA_STR + k8 + 4 + t]);
            }
            uint32_t bf[4][2];
#pragma unroll
            for (int nt = 0; nt < 4; nt++) {
                const int n = wn + nt * 8 + g;
                bf[nt][0] = __float_as_uint(sB[(k8 + t) * AVB_STR + n]);
                bf[nt][1] = __float_as_uint(sB[(k8 + 4 + t) * AVB_STR + n]);
            }
#pragma unroll
            for (int mt = 0; mt < 2; mt++)
#pragma unroll
                for (int nt = 0; nt < 4; nt++)
                    mma_tf32(acc[mt][nt], af[mt][0], af[mt][1], af[mt][2], af[mt][3],
                             bf[nt][0], bf[nt][1]);
        }
        __syncthreads();
    }

#pragma unroll
    for (int mt = 0; mt < 2; mt++) {
        const int ra = row0 + wm + mt * 16 + g;
#pragma unroll
        for (int nt = 0; nt < 4; nt++) {
            const int cc = wn + nt * 8 + 2 * t;
            float* dst0 = ctx + (size_t)(b * SS + ra) * DD + h * DH + cc;
            float* dst1 = ctx + (size_t)(b * SS + ra + 8) * DD + h * DH + cc;
            *(float2*)dst0 = make_float2(rnd_tf32(acc[mt][nt][0]), rnd_tf32(acc[mt][nt][1]));
            *(float2*)dst1 = make_float2(rnd_tf32(acc[mt][nt][2]), rnd_tf32(acc[mt][nt][3]));
        }
    }
}

// ============================================================================
// In-place row softmax over rows of 1024; writes tf32-rounded weights.
// ============================================================================
__global__ __launch_bounds__(256) void softmax_rows(float* __restrict__ w)
{
    float* p = w + (size_t)blockIdx.x * SS;
    const int tid = threadIdx.x;
    float4 v = *(const float4*)(p + tid * 4);

    float m = fmaxf(fmaxf(v.x, v.y), fmaxf(v.z, v.w));
#pragma unroll
    for (int o = 16; o; o >>= 1) m = fmaxf(m, __shfl_xor_sync(0xffffffffu, m, o));
    __shared__ float smax[8];
    __shared__ float ssum[8];
    if ((tid & 31) == 0) smax[tid >> 5] = m;
    __syncthreads();
    float bm = smax[0];
#pragma unroll
    for (int i = 1; i < 8; i++) bm = fmaxf(bm, smax[i]);

    float e0 = expf(v.x - bm), e1 = expf(v.y - bm);
    float e2 = expf(v.z - bm), e3 = expf(v.w - bm);
    float s = e0 + e1 + e2 + e3;
#pragma unroll
    for (int o = 16; o; o >>= 1) s += __shfl_xor_sync(0xffffffffu, s, o);
    if ((tid & 31) == 0) ssum[tid >> 5] = s;
    __syncthreads();
    float tot = 0.f;
#pragma unroll
    for (int i = 0; i < 8; i++) tot += ssum[i];
    float inv = 1.f / tot;

    float4 o4;
    o4.x = rnd_tf32(e0 * inv); o4.y = rnd_tf32(e1 * inv);
    o4.z = rnd_tf32(e2 * inv); o4.w = rnd_tf32(e3 * inv);
    *(float4*)(p + tid * 4) = o4;
}

// ============================================================================
// Fused residual add + LayerNorm; optional tf32-rounded twin output.
// ============================================================================
__global__ __launch_bounds__(256) void add_ln(
    const float* __restrict__ a, const float* __restrict__ r,
    const float* __restrict__ g, const float* __restrict__ beta,
    float* __restrict__ out, float* __restrict__ outr)
{
    const size_t base = (size_t)blockIdx.x * DD;
    const int tid = threadIdx.x;
    float4 va = *(const float4*)(a + base + tid * 4);
    float4 vr = *(const float4*)(r + base + tid * 4);
    float x0 = va.x + vr.x, x1 = va.y + vr.y, x2 = va.z + vr.z, x3 = va.w + vr.w;

    float s = x0 + x1 + x2 + x3;
    float sq = x0 * x0 + x1 * x1 + x2 * x2 + x3 * x3;
#pragma unroll
    for (int o = 16; o; o >>= 1) {
        s  += __shfl_xor_sync(0xffffffffu, s, o);
        sq += __shfl_xor_sync(0xffffffffu, sq, o);
    }
    __shared__ float ss[8], ssq[8];
    if ((tid & 31) == 0) { ss[tid >> 5] = s; ssq[tid >> 5] = sq; }
    __syncthreads();
    float ts = 0.f, tsq = 0.f;
#pragma unroll
    for (int i = 0; i < 8; i++) { ts += ss[i]; tsq += ssq[i]; }
    const float mu = ts * (1.0f / DD);
    const float var = tsq * (1.0f / DD) - mu * mu;
    const float rs = rsqrtf(var + LN_EPS);

    float4 gg = *(const float4*)(g + tid * 4);
    float4 bb = *(const float4*)(beta + tid * 4);
    float4 o4;
    o4.x = (x0 - mu) * rs * gg.x + bb.x;
    o4.y = (x1 - mu) * rs * gg.y + bb.y;
    o4.z = (x2 - mu) * rs * gg.z + bb.z;
    o4.w = (x3 - mu) * rs * gg.w + bb.w;
    *(float4*)(out + base + tid * 4) = o4;
    if (outr) {
        float4 q4;
        q4.x = rnd_tf32(o4.x); q4.y = rnd_tf32(o4.y);
        q4.z = rnd_tf32(o4.z); q4.w = rnd_tf32(o4.w);
        *(float4*)(outr + base + tid * 4) = q4;
    }
}

// ============================================================================
// Host launch
// ============================================================================
extern "C" void kernel_launch(void* const* d_in, const int* in_sizes, int n_in,
                              void* d_out, int out_size)
{
    (void)in_sizes; (void)n_in; (void)out_size;
    const float* x    = (const float*)d_in[0];
    const float* enc  = (const float*)d_in[1];
    const float* pad  = (const float*)d_in[2];
    const float* sub  = (const float*)d_in[3];
    const float* wq1w = (const float*)d_in[4];   const float* wq1b = (const float*)d_in[5];
    const float* wk1w = (const float*)d_in[6];   const float* wk1b = (const float*)d_in[7];
    const float* wv1w = (const float*)d_in[8];   const float* wv1b = (const float*)d_in[9];
    const float* wo1w = (const float*)d_in[10];  const float* wo1b = (const float*)d_in[11];
    const float* wq2w = (const float*)d_in[12];  const float* wq2b = (const float*)d_in[13];
    const float* wk2w = (const float*)d_in[14];  const float* wk2b = (const float*)d_in[15];
    const float* wv2w = (const float*)d_in[16];  const float* wv2b = (const float*)d_in[17];
    const float* wo2w = (const float*)d_in[18];  const float* wo2b = (const float*)d_in[19];
    const float* f1w  = (const float*)d_in[20];  const float* f1b  = (const float*)d_in[21];
    const float* f2w  = (const float*)d_in[22];  const float* f2b  = (const float*)d_in[23];
    const float* ln1g = (const float*)d_in[24];  const float* ln1b = (const float*)d_in[25];
    const float* ln2g = (const float*)d_in[26];  const float* ln2b = (const float*)d_in[27];
    const float* ln3g = (const float*)d_in[28];  const float* ln3b = (const float*)d_in[29];

    static float *q_p, *k_p, *v_p, *ctx_p, *mha_p, *res1_p, *res2_p, *ffn_p;
    static float *wt_p, *xr_p, *encr_p, *res1r_p, *res2r_p;
    static bool init = false;
    if (!init) {
        cudaGetSymbolAddress((void**)&q_p, g_q);
        cudaGetSymbolAddress((void**)&k_p, g_k);
        cudaGetSymbolAddress((void**)&v_p, g_v);
        cudaGetSymbolAddress((void**)&ctx_p, g_ctx);
        cudaGetSymbolAddress((void**)&mha_p, g_mha);
        cudaGetSymbolAddress((void**)&res1_p, g_res1);
        cudaGetSymbolAddress((void**)&res2_p, g_res2);
        cudaGetSymbolAddress((void**)&ffn_p, g_ffn);
        cudaGetSymbolAddress((void**)&wt_p, g_wt);
        cudaGetSymbolAddress((void**)&xr_p, g_xr);
        cudaGetSymbolAddress((void**)&encr_p, g_encr);
        cudaGetSymbolAddress((void**)&res1r_p, g_res1r);
        cudaGetSymbolAddress((void**)&res2r_p, g_res2r);
        cudaFuncSetAttribute(gemm_ca<false,false>,
            cudaFuncAttributeMaxDynamicSharedMemorySize, GEMM_SMEM_BYTES);
        cudaFuncSetAttribute(gemm_ca<false,true>,
            cudaFuncAttributeMaxDynamicSharedMemorySize, GEMM_SMEM_BYTES);
        cudaFuncSetAttribute(gemm_ca<true,true>,
            cudaFuncAttributeMaxDynamicSharedMemorySize, GEMM_SMEM_BYTES);
        cudaFuncSetAttribute(attn_logits2,
            cudaFuncAttributeMaxDynamicSharedMemorySize, LOG_SMEM_BYTES);
        cudaFuncSetAttribute(attn_av_ca,
            cudaFuncAttributeMaxDynamicSharedMemorySize, AV_SMEM_BYTES);
        init = true;
    }

    // rounded weight slots (floats)
    const size_t M1 = 1024u * 1024u;
    float* t_q1 = wt_p + 0*M1;  float* t_k1 = wt_p + 1*M1;
    float* t_v1 = wt_p + 2*M1;  float* t_o1 = wt_p + 3*M1;
    float* t_q2 = wt_p + 4*M1;  float* t_k2 = wt_p + 5*M1;
    float* t_v2 = wt_p + 6*M1;  float* t_o2 = wt_p + 7*M1;
    float* t_f1 = wt_p + 8*M1;   // 4M floats
    float* t_f2 = wt_p + 12*M1;  // 4M floats

    // Output layout: out3 | attn_w1 | attn_w2
    float* out3 = (float*)d_out;
    float* aw1  = out3 + (size_t)MM * DD;
    float* aw2  = aw1 + (size_t)BB * HH * SS * SS;

    const int RB = 256;
    const int G1 = (int)(M1 / 4 / RB);          // 1024 blocks per 1M-float tensor
    round_tf32_k<<<G1, RB>>>((const float4*)wq1w, (float4*)t_q1);
    round_tf32_k<<<G1, RB>>>((const float4*)wk1w, (float4*)t_k1);
    round_tf32_k<<<G1, RB>>>((const float4*)wv1w, (float4*)t_v1);
    round_tf32_k<<<G1, RB>>>((const float4*)wo1w, (float4*)t_o1);
    round_tf32_k<<<G1, RB>>>((const float4*)wq2w, (float4*)t_q2);
    round_tf32_k<<<G1, RB>>>((const float4*)wk2w, (float4*)t_k2);
    round_tf32_k<<<G1, RB>>>((const float4*)wv2w, (float4*)t_v2);
    round_tf32_k<<<G1, RB>>>((const float4*)wo2w, (float4*)t_o2);
    round_tf32_k<<<4*G1, RB>>>((const float4*)f1w, (float4*)t_f1);
    round_tf32_k<<<4*G1, RB>>>((const float4*)f2w, (float4*)t_f2);
    round_tf32_k<<<4*G1, RB>>>((const float4*)x,   (float4*)xr_p);
    round_tf32_k<<<4*G1, RB>>>((const float4*)enc, (float4*)encr_p);

    const dim3 gD(DD / 128, MM / 128);
    const dim3 gF(DFF / 128, MM / 128);
    const dim3 gLog(SS / 128, SS / 128, BB * HH);
    const dim3 gAV(SS / 128, BB * HH);
    const int nRowsAttn = BB * HH * SS;

    // ---- MHA1 (self-attention) ----
    gemm_ca<false,false><<<gD, 256, GEMM_SMEM_BYTES>>>(xr_p, t_q1, wq1b, q_p, MM, DD, DD);
    gemm_ca<false,true ><<<gD, 256, GEMM_SMEM_BYTES>>>(xr_p, t_k1, wk1b, k_p, MM, DD, DD);
    gemm_ca<false,true ><<<gD, 256, GEMM_SMEM_BYTES>>>(xr_p, t_v1, wv1b, v_p, MM, DD, DD);
    attn_logits2<<<gLog, 256, LOG_SMEM_BYTES>>>(q_p, k_p, sub, aw1);
    softmax_rows<<<nRowsAttn, 256>>>(aw1);
    attn_av_ca<<<gAV, 256, AV_SMEM_BYTES>>>(aw1, v_p, ctx_p);
    gemm_ca<false,false><<<gD, 256, GEMM_SMEM_BYTES>>>(ctx_p, t_o1, wo1b, mha_p, MM, DD, DD);
    add_ln<<<MM, 256>>>(mha_p, x, ln1g, ln1b, res1_p, res1r_p);

    // ---- MHA2 (cross-attention) ----
    gemm_ca<false,false><<<gD, 256, GEMM_SMEM_BYTES>>>(res1r_p, t_q2, wq2b, q_p, MM, DD, DD);
    gemm_ca<false,true ><<<gD, 256, GEMM_SMEM_BYTES>>>(encr_p, t_k2, wk2b, k_p, MM, DD, DD);
    gemm_ca<false,true ><<<gD, 256, GEMM_SMEM_BYTES>>>(encr_p, t_v2, wv2b, v_p, MM, DD, DD);
    attn_logits2<<<gLog, 256, LOG_SMEM_BYTES>>>(q_p, k_p, pad, aw2);
    softmax_rows<<<nRowsAttn, 256>>>(aw2);
    attn_av_ca<<<gAV, 256, AV_SMEM_BYTES>>>(aw2, v_p, ctx_p);
    gemm_ca<false,false><<<gD, 256, GEMM_SMEM_BYTES>>>(ctx_p, t_o2, wo2b, mha_p, MM, DD, DD);
    add_ln<<<MM, 256>>>(mha_p, res1_p, ln2g, ln2b, res2_p, res2r_p);

    // ---- FFN ----
    gemm_ca<true ,true ><<<gF, 256, GEMM_SMEM_BYTES>>>(res2r_p, t_f1, f1b, ffn_p, MM, DFF, DD);
    gemm_ca<false,false><<<gD, 256, GEMM_SMEM_BYTES>>>(ffn_p, t_f2, f2b, mha_p, MM, DD, DFF);
    add_ln<<<MM, 256>>>(mha_p, res2_p, ln3g, ln3b, out3, nullptr);
}

// round 8
// speedup vs baseline: 3.0020x; 1.0303x over previous
#include <cuda_runtime.h>
#include <cstdint>
#include <math.h>

// Problem constants
#define BB   4
#define SS   1024
#define DD   1024
#define HH   16
#define DH   64
#define DFF  4096
#define MM   (BB*SS)          // 4096 rows
#define LN_EPS 1e-5f

// -------------------- scratch (static device globals; no runtime alloc) ----
__device__ float g_q[MM*DD];
__device__ float g_k[MM*DD];
__device__ float g_v[MM*DD];
__device__ float g_ctx[MM*DD];
__device__ float g_mha[MM*DD];
__device__ float g_res1[MM*DD];
__device__ float g_res2[MM*DD];
__device__ float g_ffn[(size_t)MM*DFF];
__device__ float g_wt[16u*1024u*1024u];   // tf32-rounded weights (concatenated)
__device__ float g_xr[MM*DD];
__device__ float g_encr[MM*DD];
__device__ float g_res1r[MM*DD];
__device__ float g_res2r[MM*DD];

__device__ __forceinline__ uint32_t cvt_tf32(float f) {
    uint32_t r;
    asm("cvt.rna.tf32.f32 %0, %1;" : "=r"(r) : "f"(f));
    return r;
}
__device__ __forceinline__ float rnd_tf32(float f) {
    return __uint_as_float(cvt_tf32(f));
}
__device__ __forceinline__ uint32_t smem_u32(const void* p) {
    uint32_t a;
    asm("{ .reg .u64 t; cvta.to.shared.u64 t, %1; cvt.u32.u64 %0, t; }"
        : "=r"(a) : "l"(p));
    return a;
}
__device__ __forceinline__ void cp16(uint32_t dst, const void* src) {
    asm volatile("cp.async.ca.shared.global [%0], [%1], 16;" :: "r"(dst), "l"(src));
}
#define CP_COMMIT() asm volatile("cp.async.commit_group;")
#define CP_WAIT0()  asm volatile("cp.async.wait_group 0;")

__device__ __forceinline__ void mma_tf32(float* c,
    uint32_t a0, uint32_t a1, uint32_t a2, uint32_t a3,
    uint32_t b0, uint32_t b1)
{
    asm volatile(
        "mma.sync.aligned.m16n8k8.row.col.f32.tf32.tf32.f32 "
        "{%0,%1,%2,%3}, {%4,%5,%6,%7}, {%8,%9}, {%0,%1,%2,%3};"
        : "+f"(c[0]), "+f"(c[1]), "+f"(c[2]), "+f"(c[3])
        : "r"(a0), "r"(a1), "r"(a2), "r"(a3), "r"(b0), "r"(b1));
}

// ============================================================================
// Merged tf32 rounding: 12 tensors, one launch. Each block = 4096 floats.
// ============================================================================
struct R12 {
    const float4* src[12];
    float4* dst[12];
    int cum[13];
};

__global__ __launch_bounds__(256) void round_all(R12 r)
{
    const int bid = blockIdx.x;
    int ti = 0;
#pragma unroll
    for (int i = 0; i < 12; i++)
        if (bid >= r.cum[i + 1]) ti = i + 1;
    const float4* s = r.src[ti];
    float4* d = r.dst[ti];
    const int base = (bid - r.cum[ti]) * 1024 + threadIdx.x;
#pragma unroll
    for (int j = 0; j < 4; j++) {
        const int idx = base + j * 256;
        float4 v = s[idx];
        float4 o;
        o.x = rnd_tf32(v.x); o.y = rnd_tf32(v.y);
        o.z = rnd_tf32(v.z); o.w = rnd_tf32(v.w);
        d[idx] = o;
    }
}

// ============================================================================
// GEMM body: C = A@W + bias, optional ReLU (template), runtime tf32-round.
// CTA 128x128, BK=32, 256 thr = 8 warps (4x2), warp tile 32x64.
// Race-free pipeline: wait0 -> sync -> issue-next -> compute.
// ============================================================================
#define AS_STR 36
#define BS_STR 136
#define A_FLTS (128*AS_STR)
#define B_FLTS (32*BS_STR)
#define BUF_FLTS (A_FLTS + B_FLTS)       // 8960
#define GEMM_SMEM_BYTES (2*BUF_FLTS*4)   // 71680

template<bool RELU>
__device__ __forceinline__ void gemm_body(
    const float* __restrict__ A, const float* __restrict__ W,
    const float* __restrict__ bias, float* __restrict__ C,
    int N, int K, bool round_out,
    float* sm, int row0, int col0)
{
    const uint32_t smb = smem_u32(sm);
    const int tid = threadIdx.x;
    const int wid = tid >> 5, lane = tid & 31;
    const int g = lane >> 2, t = lane & 3;
    const int wm = (wid >> 1) * 32;
    const int wn = (wid & 1) * 64;

    int a_row[4], a_c4[4], b_k[4], b_n4[4];
#pragma unroll
    for (int it = 0; it < 4; it++) {
        int lin = it * 256 + tid;
        a_row[it] = lin >> 3;
        a_c4[it]  = (lin & 7) * 4;
        b_k[it]   = lin >> 5;
        b_n4[it]  = (lin & 31) * 4;
    }

    float acc[2][8][4];
#pragma unroll
    for (int mt = 0; mt < 2; mt++)
#pragma unroll
        for (int nt = 0; nt < 8; nt++)
#pragma unroll
            for (int i = 0; i < 4; i++) acc[mt][nt][i] = 0.f;

    const int nchunk = K >> 5;

    {
        const uint32_t ab = smb, bb = smb + A_FLTS * 4;
#pragma unroll
        for (int it = 0; it < 4; it++) {
            cp16(ab + (a_row[it] * AS_STR + a_c4[it]) * 4,
                 A + (size_t)(row0 + a_row[it]) * K + a_c4[it]);
            cp16(bb + (b_k[it] * BS_STR + b_n4[it]) * 4,
                 W + (size_t)b_k[it] * N + col0 + b_n4[it]);
        }
        CP_COMMIT();
    }

    for (int ic = 0; ic < nchunk; ic++) {
        const int p = ic & 1;
        CP_WAIT0();
        __syncthreads();
        if (ic + 1 < nchunk) {
            const int k1 = (ic + 1) << 5;
            const uint32_t ab = smb + (p ? 0 : BUF_FLTS * 4);
            const uint32_t bb = ab + A_FLTS * 4;
#pragma unroll
            for (int it = 0; it < 4; it++) {
                cp16(ab + (a_row[it] * AS_STR + a_c4[it]) * 4,
                     A + (size_t)(row0 + a_row[it]) * K + k1 + a_c4[it]);
                cp16(bb + (b_k[it] * BS_STR + b_n4[it]) * 4,
                     W + (size_t)(k1 + b_k[it]) * N + col0 + b_n4[it]);
            }
            CP_COMMIT();
        }

        const float* sA = sm + (p ? BUF_FLTS : 0);
        const float* sB = sA + A_FLTS;
#pragma unroll
        for (int ks = 0; ks < 4; ks++) {
            const int k8 = ks * 8;
            uint32_t af[2][4];
#pragma unroll
            for (int mt = 0; mt < 2; mt++) {
                const int r = wm + mt * 16 + g;
                af[mt][0] = __float_as_uint(sA[r * AS_STR + k8 + t]);
                af[mt][1] = __float_as_uint(sA[(r + 8) * AS_STR + k8 + t]);
                af[mt][2] = __float_as_uint(sA[r * AS_STR + k8 + 4 + t]);
                af[mt][3] = __float_as_uint(sA[(r + 8) * AS_STR + k8 + 4 + t]);
            }
            uint32_t bf[8][2];
#pragma unroll
            for (int nt = 0; nt < 8; nt++) {
                const int n = wn + nt * 8 + g;
                bf[nt][0] = __float_as_uint(sB[(k8 + t) * BS_STR + n]);
                bf[nt][1] = __float_as_uint(sB[(k8 + 4 + t) * BS_STR + n]);
            }
#pragma unroll
            for (int mt = 0; mt < 2; mt++)
#pragma unroll
                for (int nt = 0; nt < 8; nt++)
                    mma_tf32(acc[mt][nt], af[mt][0], af[mt][1], af[mt][2], af[mt][3],
                             bf[nt][0], bf[nt][1]);
        }
    }

#pragma unroll
    for (int mt = 0; mt < 2; mt++) {
        const int ra = row0 + wm + mt * 16 + g;
#pragma unroll
        for (int nt = 0; nt < 8; nt++) {
            const int cc = col0 + wn + nt * 8 + 2 * t;
            float2 bv = *(const float2*)(bias + cc);
            float v0 = acc[mt][nt][0] + bv.x;
            float v1 = acc[mt][nt][1] + bv.y;
            float v2 = acc[mt][nt][2] + bv.x;
            float v3 = acc[mt][nt][3] + bv.y;
            if (RELU) {
                v0 = fmaxf(v0, 0.f); v1 = fmaxf(v1, 0.f);
                v2 = fmaxf(v2, 0.f); v3 = fmaxf(v3, 0.f);
            }
            if (round_out) {
                v0 = rnd_tf32(v0); v1 = rnd_tf32(v1);
                v2 = rnd_tf32(v2); v3 = rnd_tf32(v3);
            }
            *(float2*)(C + (size_t)ra * N + cc) = make_float2(v0, v1);
            *(float2*)(C + (size_t)(ra + 8) * N + cc) = make_float2(v2, v3);
        }
    }
}

template<bool RELU>
__global__ void __launch_bounds__(256, 2) gemm_ca(
    const float* __restrict__ A, const float* __restrict__ W,
    const float* __restrict__ bias, float* __restrict__ C,
    int N, int K, int round_out)
{
    extern __shared__ float sm[];
    gemm_body<RELU>(A, W, bias, C, N, K, round_out != 0,
                    sm, blockIdx.y * 128, blockIdx.x * 128);
}

// Batched QKV projection: z in {0,1,2} selects (A, W, bias, C, round flag).
struct QKV {
    const float* A[3];
    const float* W[3];
    const float* b[3];
    float* C[3];
    int round_flag[3];
};

__global__ void __launch_bounds__(256, 2) gemm_qkv(QKV q)
{
    extern __shared__ float sm[];
    const int z = blockIdx.z;
    gemm_body<false>(q.A[z], q.W[z], q.b[z], q.C[z], DD, DD,
                     q.round_flag[z] != 0, sm, blockIdx.y * 128, blockIdx.x * 128);
}

// ============================================================================
// Attention logits: out = QK^T/8 + mask. Q split hi/lo (exact), K plain tf32.
// CTA 128x128 per (bh), K=64 one shot. SMEM 104.4KB -> 2 CTAs/SM.
// ============================================================================
#define L2_STR 68
#define LOG_SMEM_BYTES (3*128*L2_STR*4)   // 104448

__global__ void __launch_bounds__(256, 2) attn_logits2(
    const float* __restrict__ q, const float* __restrict__ k,
    const float* __restrict__ mask, float* __restrict__ out)
{
    extern __shared__ float sm[];
    float* Qhi = sm;
    float* Qlo = Qhi + 128 * L2_STR;
    float* Ks  = Qlo + 128 * L2_STR;
    const uint32_t ks_u32 = smem_u32(Ks);

    const int tid = threadIdx.x;
    const int wid = tid >> 5, lane = tid & 31;
    const int g = lane >> 2, t = lane & 3;
    const int wm = (wid >> 1) * 32;
    const int wn = (wid & 1) * 64;

    const int bh = blockIdx.z;
    const int b = bh >> 4, h = bh & 15;
    const int row0 = blockIdx.y * 128, col0 = blockIdx.x * 128;
    const float* qb = q + (size_t)b * SS * DD + h * DH;
    const float* kb = k + (size_t)b * SS * DD + h * DH;

#pragma unroll
    for (int it = 0; it < 8; it++) {
        const int lin = it * 256 + tid;
        const int n = lin >> 4, c4 = (lin & 15) * 4;
        cp16(ks_u32 + (n * L2_STR + c4) * 4,
             kb + (size_t)(col0 + n) * DD + c4);
    }
    CP_COMMIT();

#pragma unroll
    for (int it = 0; it < 8; it++) {
        const int lin = it * 256 + tid;
        const int r = lin >> 4, c4 = (lin & 15) * 4;
        float4 v = *(const float4*)(qb + (size_t)(row0 + r) * DD + c4);
        float vv[4] = {v.x, v.y, v.z, v.w};
#pragma unroll
        for (int j = 0; j < 4; j++) {
            float hi = rnd_tf32(vv[j]);
            Qhi[r * L2_STR + c4 + j] = hi;
            Qlo[r * L2_STR + c4 + j] = rnd_tf32(vv[j] - hi);
        }
    }
    CP_WAIT0();
    __syncthreads();

    float acc[2][8][4];
#pragma unroll
    for (int mt = 0; mt < 2; mt++)
#pragma unroll
        for (int nt = 0; nt < 8; nt++)
#pragma unroll
            for (int i = 0; i < 4; i++) acc[mt][nt][i] = 0.f;

#pragma unroll
    for (int ks = 0; ks < 8; ks++) {
        const int k8 = ks * 8;
        uint32_t ah[2][4], al[2][4];
#pragma unroll
        for (int mt = 0; mt < 2; mt++) {
            const int r = wm + mt * 16 + g;
            ah[mt][0] = __float_as_uint(Qhi[r * L2_STR + k8 + t]);
            ah[mt][1] = __float_as_uint(Qhi[(r + 8) * L2_STR + k8 + t]);
            ah[mt][2] = __float_as_uint(Qhi[r * L2_STR + k8 + 4 + t]);
            ah[mt][3] = __float_as_uint(Qhi[(r + 8) * L2_STR + k8 + 4 + t]);
            al[mt][0] = __float_as_uint(Qlo[r * L2_STR + k8 + t]);
            al[mt][1] = __float_as_uint(Qlo[(r + 8) * L2_STR + k8 + t]);
            al[mt][2] = __float_as_uint(Qlo[r * L2_STR + k8 + 4 + t]);
            al[mt][3] = __float_as_uint(Qlo[(r + 8) * L2_STR + k8 + 4 + t]);
        }
#pragma unroll
        for (int nt = 0; nt < 8; nt++) {
            const int n = wn + nt * 8 + g;
            uint32_t b0 = __float_as_uint(Ks[n * L2_STR + k8 + t]);
            uint32_t b1 = __float_as_uint(Ks[n * L2_STR + k8 + 4 + t]);
#pragma unroll
            for (int mt = 0; mt < 2; mt++) {
                mma_tf32(acc[mt][nt], al[mt][0], al[mt][1], al[mt][2], al[mt][3], b0, b1);
                mma_tf32(acc[mt][nt], ah[mt][0], ah[mt][1], ah[mt][2], ah[mt][3], b0, b1);
            }
        }
    }

    const float* mb = mask + (size_t)b * SS * SS;
    float* ob = out + (size_t)bh * SS * SS;
#pragma unroll
    for (int mt = 0; mt < 2; mt++) {
        const int r = row0 + wm + mt * 16 + g;
#pragma unroll
        for (int nt = 0; nt < 8; nt++) {
            const int c = col0 + wn + nt * 8 + 2 * t;
            float2 m0 = *(const float2*)(mb + (size_t)r * SS + c);
            float2 m1 = *(const float2*)(mb + (size_t)(r + 8) * SS + c);
            *(float2*)(ob + (size_t)r * SS + c) =
                make_float2(acc[mt][nt][0] * 0.125f + m0.x,
                            acc[mt][nt][1] * 0.125f + m0.y);
            *(float2*)(ob + (size_t)(r + 8) * SS + c) =
                make_float2(acc[mt][nt][2] * 0.125f + m1.x,
                            acc[mt][nt][3] * 0.125f + m1.y);
        }
    }
}

// ============================================================================
// Batched AV w/ cp.async. Race-free pipeline. CTA 128x64, warp 32x32.
// ============================================================================
#define AVA_STR 36
#define AVB_STR 72
#define AV_A_FLTS (128*AVA_STR)
#define AV_B_FLTS (32*AVB_STR)
#define AV_BUF (AV_A_FLTS + AV_B_FLTS)   // 6912
#define AV_SMEM_BYTES (2*AV_BUF*4)       // 55296

__global__ void __launch_bounds__(256, 2) attn_av_ca(
    const float* __restrict__ w, const float* __restrict__ v,
    float* __restrict__ ctx)
{
    extern __shared__ float sm[];
    const uint32_t smb = smem_u32(sm);
    const int tid = threadIdx.x;
    const int wid = tid >> 5, lane = tid & 31;
    const int g = lane >> 2, t = lane & 3;
    const int wm = (wid >> 1) * 32;
    const int wn = (wid & 1) * 32;

    const int bh = blockIdx.y;
    const int b = bh >> 4, h = bh & 15;
    const int row0 = blockIdx.x * 128;
    const float* wb = w + (size_t)bh * SS * SS;
    const float* vb = v + (size_t)b * SS * DD + h * DH;

    int a_row[4], a_c4[4], b_k[2], b_n4[2];
#pragma unroll
    for (int it = 0; it < 4; it++) {
        int lin = it * 256 + tid;
        a_row[it] = lin >> 3;
        a_c4[it]  = (lin & 7) * 4;
    }
#pragma unroll
    for (int it = 0; it < 2; it++) {
        int lin = it * 256 + tid;
        b_k[it]  = lin >> 4;
        b_n4[it] = (lin & 15) * 4;
    }

    float acc[2][4][4];
#pragma unroll
    for (int mt = 0; mt < 2; mt++)
#pragma unroll
        for (int nt = 0; nt < 4; nt++)
#pragma unroll
            for (int i = 0; i < 4; i++) acc[mt][nt][i] = 0.f;

    {
        const uint32_t ab = smb, bb = smb + AV_A_FLTS * 4;
#pragma unroll
        for (int it = 0; it < 4; it++)
            cp16(ab + (a_row[it] * AVA_STR + a_c4[it]) * 4,
                 wb + (size_t)(row0 + a_row[it]) * SS + a_c4[it]);
#pragma unroll
        for (int it = 0; it < 2; it++)
            cp16(bb + (b_k[it] * AVB_STR + b_n4[it]) * 4,
                 vb + (size_t)b_k[it] * DD + b_n4[it]);
        CP_COMMIT();
    }

    for (int ic = 0; ic < 32; ic++) {
        const int p = ic & 1;
        CP_WAIT0();
        __syncthreads();
        if (ic + 1 < 32) {
            const int k1 = (ic + 1) << 5;
            const uint32_t ab = smb + (p ? 0 : AV_BUF * 4);
            const uint32_t bb = ab + AV_A_FLTS * 4;
#pragma unroll
            for (int it = 0; it < 4; it++)
                cp16(ab + (a_row[it] * AVA_STR + a_c4[it]) * 4,
                     wb + (size_t)(row0 + a_row[it]) * SS + k1 + a_c4[it]);
#pragma unroll
            for (int it = 0; it < 2; it++)
                cp16(bb + (b_k[it] * AVB_STR + b_n4[it]) * 4,
                     vb + (size_t)(k1 + b_k[it]) * DD + b_n4[it]);
            CP_COMMIT();
        }

        const float* sA = sm + (p ? AV_BUF : 0);
        const float* sB = sA + AV_A_FLTS;
#pragma unroll
        for (int ks = 0; ks < 4; ks++) {
            const int k8 = ks * 8;
            uint32_t af[2][4];
#pragma unroll
            for (int mt = 0; mt < 2; mt++) {
                const int r = wm + mt * 16 + g;
                af[mt][0] = __float_as_uint(sA[r * AVA_STR + k8 + t]);
                af[mt][1] = __float_as_uint(sA[(r + 8) * AVA_STR + k8 + t]);
                af[mt][2] = __float_as_uint(sA[r * AVA_STR + k8 + 4 + t]);
                af[mt][3] = __float_as_uint(sA[(r + 8) * AVA_STR + k8 + 4 + t]);
            }
            uint32_t bf[4][2];
#pragma unroll
            for (int nt = 0; nt < 4; nt++) {
                const int n = wn + nt * 8 + g;
                bf[nt][0] = __float_as_uint(sB[(k8 + t) * AVB_STR + n]);
                bf[nt][1] = __float_as_uint(sB[(k8 + 4 + t) * AVB_STR + n]);
            }
#pragma unroll
            for (int mt = 0; mt < 2; mt++)
#pragma unroll
                for (int nt = 0; nt < 4; nt++)
                    mma_tf32(acc[mt][nt], af[mt][0], af[mt][1], af[mt][2], af[mt][3],
                             bf[nt][0], bf[nt][1]);
        }
    }

#pragma unroll
    for (int mt = 0; mt < 2; mt++) {
        const int ra = row0 + wm + mt * 16 + g;
#pragma unroll
        for (int nt = 0; nt < 4; nt++) {
            const int cc = wn + nt * 8 + 2 * t;
            float* dst0 = ctx + (size_t)(b * SS + ra) * DD + h * DH + cc;
            float* dst1 = ctx + (size_t)(b * SS + ra + 8) * DD + h * DH + cc;
            *(float2*)dst0 = make_float2(rnd_tf32(acc[mt][nt][0]), rnd_tf32(acc[mt][nt][1]));
            *(float2*)dst1 = make_float2(rnd_tf32(acc[mt][nt][2]), rnd_tf32(acc[mt][nt][3]));
        }
    }
}

// ============================================================================
// Softmax: warp-per-row (8 rows/block). Each lane owns 8 float4 (32 values)
// covering the FULL 1024-wide row. __expf; writes tf32-rounded weights.
// ============================================================================
__global__ __launch_bounds__(256) void softmax_rows_w(float* __restrict__ w)
{
    const int row = blockIdx.x * 8 + (threadIdx.x >> 5);
    const int lane = threadIdx.x & 31;
    float* p = w + (size_t)row * SS;

    float4 v[8];
#pragma unroll
    for (int j = 0; j < 8; j++)
        v[j] = *(const float4*)(p + lane * 4 + j * 128);

    float m = -1e30f;
#pragma unroll
    for (int j = 0; j < 8; j++)
        m = fmaxf(m, fmaxf(fmaxf(v[j].x, v[j].y), fmaxf(v[j].z, v[j].w)));
#pragma unroll
    for (int o = 16; o; o >>= 1) m = fmaxf(m, __shfl_xor_sync(0xffffffffu, m, o));

    float s = 0.f;
#pragma unroll
    for (int j = 0; j < 8; j++) {
        v[j].x = __expf(v[j].x - m); v[j].y = __expf(v[j].y - m);
        v[j].z = __expf(v[j].z - m); v[j].w = __expf(v[j].w - m);
        s += (v[j].x + v[j].y) + (v[j].z + v[j].w);
    }
#pragma unroll
    for (int o = 16; o; o >>= 1) s += __shfl_xor_sync(0xffffffffu, s, o);
    const float inv = 1.f / s;

#pragma unroll
    for (int j = 0; j < 8; j++) {
        float4 o4;
        o4.x = rnd_tf32(v[j].x * inv); o4.y = rnd_tf32(v[j].y * inv);
        o4.z = rnd_tf32(v[j].z * inv); o4.w = rnd_tf32(v[j].w * inv);
        *(float4*)(p + lane * 4 + j * 128) = o4;
    }
}

// ============================================================================
// Fused residual add + LayerNorm; optional tf32-rounded twin output.
// ============================================================================
__global__ __launch_bounds__(256) void add_ln(
    const float* __restrict__ a, const float* __restrict__ r,
    const float* __restrict__ g, const float* __restrict__ beta,
    float* __restrict__ out, float* __restrict__ outr)
{
    const size_t base = (size_t)blockIdx.x * DD;
    const int tid = threadIdx.x;
    float4 va = *(const float4*)(a + base + tid * 4);
    float4 vr = *(const float4*)(r + base + tid * 4);
    float x0 = va.x + vr.x, x1 = va.y + vr.y, x2 = va.z + vr.z, x3 = va.w + vr.w;

    float s = x0 + x1 + x2 + x3;
    float sq = x0 * x0 + x1 * x1 + x2 * x2 + x3 * x3;
#pragma unroll
    for (int o = 16; o; o >>= 1) {
        s  += __shfl_xor_sync(0xffffffffu, s, o);
        sq += __shfl_xor_sync(0xffffffffu, sq, o);
    }
    __shared__ float ss[8], ssq[8];
    if ((tid & 31) == 0) { ss[tid >> 5] = s; ssq[tid >> 5] = sq; }
    __syncthreads();
    float ts = 0.f, tsq = 0.f;
#pragma unroll
    for (int i = 0; i < 8; i++) { ts += ss[i]; tsq += ssq[i]; }
    const float mu = ts * (1.0f / DD);
    const float var = tsq * (1.0f / DD) - mu * mu;
    const float rs = rsqrtf(var + LN_EPS);

    float4 gg = *(const float4*)(g + tid * 4);
    float4 bb = *(const float4*)(beta + tid * 4);
    float4 o4;
    o4.x = (x0 - mu) * rs * gg.x + bb.x;
    o4.y = (x1 - mu) * rs * gg.y + bb.y;
    o4.z = (x2 - mu) * rs * gg.z + bb.z;
    o4.w = (x3 - mu) * rs * gg.w + bb.w;
    *(float4*)(out + base + tid * 4) = o4;
    if (outr) {
        float4 q4;
        q4.x = rnd_tf32(o4.x); q4.y = rnd_tf32(o4.y);
        q4.z = rnd_tf32(o4.z); q4.w = rnd_tf32(o4.w);
        *(float4*)(outr + base + tid * 4) = q4;
    }
}

// ============================================================================
// Host launch
// ============================================================================
extern "C" void kernel_launch(void* const* d_in, const int* in_sizes, int n_in,
                              void* d_out, int out_size)
{
    (void)in_sizes; (void)n_in; (void)out_size;
    const float* x    = (const float*)d_in[0];
    const float* enc  = (const float*)d_in[1];
    const float* pad  = (const float*)d_in[2];
    const float* sub  = (const float*)d_in[3];
    const float* wq1w = (const float*)d_in[4];   const float* wq1b = (const float*)d_in[5];
    const float* wk1w = (const float*)d_in[6];   const float* wk1b = (const float*)d_in[7];
    const float* wv1w = (const float*)d_in[8];   const float* wv1b = (const float*)d_in[9];
    const float* wo1w = (const float*)d_in[10];  const float* wo1b = (const float*)d_in[11];
    const float* wq2w = (const float*)d_in[12];  const float* wq2b = (const float*)d_in[13];
    const float* wk2w = (const float*)d_in[14];  const float* wk2b = (const float*)d_in[15];
    const float* wv2w = (const float*)d_in[16];  const float* wv2b = (const float*)d_in[17];
    const float* wo2w = (const float*)d_in[18];  const float* wo2b = (const float*)d_in[19];
    const float* f1w  = (const float*)d_in[20];  const float* f1b  = (const float*)d_in[21];
    const float* f2w  = (const float*)d_in[22];  const float* f2b  = (const float*)d_in[23];
    const float* ln1g = (const float*)d_in[24];  const float* ln1b = (const float*)d_in[25];
    const float* ln2g = (const float*)d_in[26];  const float* ln2b = (const float*)d_in[27];
    const float* ln3g = (const float*)d_in[28];  const float* ln3b = (const float*)d_in[29];

    static float *q_p, *k_p, *v_p, *ctx_p, *mha_p, *res1_p, *res2_p, *ffn_p;
    static float *wt_p, *xr_p, *encr_p, *res1r_p, *res2r_p;
    static bool init = false;
    if (!init) {
        cudaGetSymbolAddress((void**)&q_p, g_q);
        cudaGetSymbolAddress((void**)&k_p, g_k);
        cudaGetSymbolAddress((void**)&v_p, g_v);
        cudaGetSymbolAddress((void**)&ctx_p, g_ctx);
        cudaGetSymbolAddress((void**)&mha_p, g_mha);
        cudaGetSymbolAddress((void**)&res1_p, g_res1);
        cudaGetSymbolAddress((void**)&res2_p, g_res2);
        cudaGetSymbolAddress((void**)&ffn_p, g_ffn);
        cudaGetSymbolAddress((void**)&wt_p, g_wt);
        cudaGetSymbolAddress((void**)&xr_p, g_xr);
        cudaGetSymbolAddress((void**)&encr_p, g_encr);
        cudaGetSymbolAddress((void**)&res1r_p, g_res1r);
        cudaGetSymbolAddress((void**)&res2r_p, g_res2r);
        cudaFuncSetAttribute(gemm_ca<false>,
            cudaFuncAttributeMaxDynamicSharedMemorySize, GEMM_SMEM_BYTES);
        cudaFuncSetAttribute(gemm_ca<true>,
            cudaFuncAttributeMaxDynamicSharedMemorySize, GEMM_SMEM_BYTES);
        cudaFuncSetAttribute(gemm_qkv,
            cudaFuncAttributeMaxDynamicSharedMemorySize, GEMM_SMEM_BYTES);
        cudaFuncSetAttribute(attn_logits2,
            cudaFuncAttributeMaxDynamicSharedMemorySize, LOG_SMEM_BYTES);
        cudaFuncSetAttribute(attn_av_ca,
            cudaFuncAttributeMaxDynamicSharedMemorySize, AV_SMEM_BYTES);
        init = true;
    }

    // rounded weight slots (floats)
    const size_t M1 = 1024u * 1024u;
    float* t_q1 = wt_p + 0*M1;  float* t_k1 = wt_p + 1*M1;
    float* t_v1 = wt_p + 2*M1;  float* t_o1 = wt_p + 3*M1;
    float* t_q2 = wt_p + 4*M1;  float* t_k2 = wt_p + 5*M1;
    float* t_v2 = wt_p + 6*M1;  float* t_o2 = wt_p + 7*M1;
    float* t_f1 = wt_p + 8*M1;
    float* t_f2 = wt_p + 12*M1;

    // Output layout: out3 | attn_w1 | attn_w2
    float* out3 = (float*)d_out;
    float* aw1  = out3 + (size_t)MM * DD;
    float* aw2  = aw1 + (size_t)BB * HH * SS * SS;

    // ---- merged rounding (one launch) ----
    R12 r12;
    const float* srcs[12] = {wq1w, wk1w, wv1w, wo1w, wq2w, wk2w, wv2w, wo2w,
                             f1w, f2w, x, enc};
    float* dsts[12] = {t_q1, t_k1, t_v1, t_o1, t_q2, t_k2, t_v2, t_o2,
                       t_f1, t_f2, xr_p, encr_p};
    int blks[12] = {256,256,256,256,256,256,256,256,1024,1024,1024,1024};
    int c = 0;
    for (int i = 0; i < 12; i++) {
        r12.src[i] = (const float4*)srcs[i];
        r12.dst[i] = (float4*)dsts[i];
        r12.cum[i] = c;
        c += blks[i];
    }
    r12.cum[12] = c;   // 6144
    round_all<<<c, 256>>>(r12);

    const dim3 gD(DD / 128, MM / 128);
    const dim3 gF(DFF / 128, MM / 128);
    const dim3 gQKV(DD / 128, MM / 128, 3);
    const dim3 gLog(SS / 128, SS / 128, BB * HH);
    const dim3 gAV(SS / 128, BB * HH);
    const int nSmBlocks = BB * HH * SS / 8;   // 8192

    // ---- MHA1 (self-attention) ----
    {
        QKV qk;
        qk.A[0] = xr_p; qk.A[1] = xr_p; qk.A[2] = xr_p;
        qk.W[0] = t_q1; qk.W[1] = t_k1; qk.W[2] = t_v1;
        qk.b[0] = wq1b; qk.b[1] = wk1b; qk.b[2] = wv1b;
        qk.C[0] = q_p;  qk.C[1] = k_p;  qk.C[2] = v_p;
        qk.round_flag[0] = 0; qk.round_flag[1] = 1; qk.round_flag[2] = 1;
        gemm_qkv<<<gQKV, 256, GEMM_SMEM_BYTES>>>(qk);
    }
    attn_logits2<<<gLog, 256, LOG_SMEM_BYTES>>>(q_p, k_p, sub, aw1);
    softmax_rows_w<<<nSmBlocks, 256>>>(aw1);
    attn_av_ca<<<gAV, 256, AV_SMEM_BYTES>>>(aw1, v_p, ctx_p);
    gemm_ca<false><<<gD, 256, GEMM_SMEM_BYTES>>>(ctx_p, t_o1, wo1b, mha_p, DD, DD, 0);
    add_ln<<<MM, 256>>>(mha_p, x, ln1g, ln1b, res1_p, res1r_p);

    // ---- MHA2 (cross-attention) ----
    {
        QKV qk;
        qk.A[0] = res1r_p; qk.A[1] = encr_p; qk.A[2] = encr_p;
        qk.W[0] = t_q2; qk.W[1] = t_k2; qk.W[2] = t_v2;
        qk.b[0] = wq2b; qk.b[1] = wk2b; qk.b[2] = wv2b;
        qk.C[0] = q_p;  qk.C[1] = k_p;  qk.C[2] = v_p;
        qk.round_flag[0] = 0; qk.round_flag[1] = 1; qk.round_flag[2] = 1;
        gemm_qkv<<<gQKV, 256, GEMM_SMEM_BYTES>>>(qk);
    }
    attn_logits2<<<gLog, 256, LOG_SMEM_BYTES>>>(q_p, k_p, pad, aw2);
    softmax_rows_w<<<nSmBlocks, 256>>>(aw2);
    attn_av_ca<<<gAV, 256, AV_SMEM_BYTES>>>(aw2, v_p, ctx_p);
    gemm_ca<false><<<gD, 256, GEMM_SMEM_BYTES>>>(ctx_p, t_o2, wo2b, mha_p, DD, DD, 0);
    add_ln<<<MM, 256>>>(mha_p, res1_p, ln2g, ln2b, res2_p, res2r_p);

    // ---- FFN ----
    gemm_ca<true ><<<gF, 256, GEMM_SMEM_BYTES>>>(res2r_p, t_f1, f1b, ffn_p, DFF, DD, 1);
    gemm_ca<false><<<gD, 256, GEMM_SMEM_BYTES>>>(ffn_p, t_f2, f2b, mha_p, DD, DFF, 0);
    add_ln<<<MM, 256>>>(mha_p, res2_p, ln3g, ln3b, out3, nullptr);
}

// round 9
// speedup vs baseline: 3.1145x; 1.0375x over previous
#include <cuda_runtime.h>
#include <cstdint>
#include <math.h>

// Problem constants
#define BB   4
#define SS   1024
#define DD   1024
#define HH   16
#define DH   64
#define DFF  4096
#define MM   (BB*SS)          // 4096 rows
#define LN_EPS 1e-5f

// -------------------- scratch (static device globals; no runtime alloc) ----
__device__ float g_q[MM*DD];
__device__ float g_k[MM*DD];
__device__ float g_v[MM*DD];
__device__ float g_ctx[MM*DD];
__device__ float g_mha[MM*DD];
__device__ float g_res1[MM*DD];
__device__ float g_res2[MM*DD];
__device__ float g_ffn[(size_t)MM*DFF];
__device__ float g_wt[16u*1024u*1024u];   // tf32-rounded weights (concatenated)
__device__ float g_xr[MM*DD];
__device__ float g_encr[MM*DD];
__device__ float g_res1r[MM*DD];
__device__ float g_res2r[MM*DD];

__device__ __forceinline__ uint32_t cvt_tf32(float f) {
    uint32_t r;
    asm("cvt.rna.tf32.f32 %0, %1;" : "=r"(r) : "f"(f));
    return r;
}
__device__ __forceinline__ float rnd_tf32(float f) {
    return __uint_as_float(cvt_tf32(f));
}
__device__ __forceinline__ uint32_t smem_u32(const void* p) {
    uint32_t a;
    asm("{ .reg .u64 t; cvta.to.shared.u64 t, %1; cvt.u32.u64 %0, t; }"
        : "=r"(a) : "l"(p));
    return a;
}
__device__ __forceinline__ void cp16(uint32_t dst, const void* src) {
    asm volatile("cp.async.ca.shared.global [%0], [%1], 16;" :: "r"(dst), "l"(src));
}
#define CP_COMMIT() asm volatile("cp.async.commit_group;")
#define CP_WAIT0()  asm volatile("cp.async.wait_group 0;")

__device__ __forceinline__ void mma_tf32(float* c,
    uint32_t a0, uint32_t a1, uint32_t a2, uint32_t a3,
    uint32_t b0, uint32_t b1)
{
    asm volatile(
        "mma.sync.aligned.m16n8k8.row.col.f32.tf32.tf32.f32 "
        "{%0,%1,%2,%3}, {%4,%5,%6,%7}, {%8,%9}, {%0,%1,%2,%3};"
        : "+f"(c[0]), "+f"(c[1]), "+f"(c[2]), "+f"(c[3])
        : "r"(a0), "r"(a1), "r"(a2), "r"(a3), "r"(b0), "r"(b1));
}

// ============================================================================
// Merged tf32 rounding: 12 tensors, one launch. Each block = 4096 floats.
// ============================================================================
struct R12 {
    const float4* src[12];
    float4* dst[12];
    int cum[13];
};

__global__ __launch_bounds__(256) void round_all(R12 r)
{
    const int bid = blockIdx.x;
    int ti = 0;
#pragma unroll
    for (int i = 0; i < 12; i++)
        if (bid >= r.cum[i + 1]) ti = i + 1;
    const float4* s = r.src[ti];
    float4* d = r.dst[ti];
    const int base = (bid - r.cum[ti]) * 1024 + threadIdx.x;
#pragma unroll
    for (int j = 0; j < 4; j++) {
        const int idx = base + j * 256;
        float4 v = s[idx];
        float4 o;
        o.x = rnd_tf32(v.x); o.y = rnd_tf32(v.y);
        o.z = rnd_tf32(v.z); o.w = rnd_tf32(v.w);
        d[idx] = o;
    }
}

// ============================================================================
// GEMM body: C = A@W + bias. CTA 128x128, BK=32, 128 threads = 4 warps (2x2),
// warp tile 64x64 (LDS/MMA ratio 1.0 -> crossbar no longer the bottleneck).
// Race-free double-buffer pipeline: wait0 -> sync -> issue-next -> compute.
// ============================================================================
#define AS_STR 36
#define BS_STR 136
#define A_FLTS (128*AS_STR)
#define B_FLTS (32*BS_STR)
#define BUF_FLTS (A_FLTS + B_FLTS)       // 8960
#define GEMM_SMEM_BYTES (2*BUF_FLTS*4)   // 71680

template<bool RELU>
__device__ __forceinline__ void gemm_body(
    const float* __restrict__ A, const float* __restrict__ W,
    const float* __restrict__ bias, float* __restrict__ C,
    int N, int K, bool round_out,
    float* sm, int row0, int col0)
{
    const uint32_t smb = smem_u32(sm);
    const int tid = threadIdx.x;              // 0..127
    const int wid = tid >> 5, lane = tid & 31;
    const int g = lane >> 2, t = lane & 3;
    const int wm = (wid >> 1) * 64;           // 2x2 warp grid, 64x64 tiles
    const int wn = (wid & 1) * 64;

    int a_row[8], a_c4[8], b_k[8], b_n4[8];
#pragma unroll
    for (int it = 0; it < 8; it++) {
        int lin = it * 128 + tid;
        a_row[it] = lin >> 3;                 // 0..127
        a_c4[it]  = (lin & 7) * 4;            // 0..28
        b_k[it]   = lin >> 5;                 // 0..31
        b_n4[it]  = (lin & 31) * 4;           // 0..124
    }

    float acc[4][8][4];
#pragma unroll
    for (int mt = 0; mt < 4; mt++)
#pragma unroll
        for (int nt = 0; nt < 8; nt++)
#pragma unroll
            for (int i = 0; i < 4; i++) acc[mt][nt][i] = 0.f;

    const int nchunk = K >> 5;

    {
        const uint32_t ab = smb, bb = smb + A_FLTS * 4;
#pragma unroll
        for (int it = 0; it < 8; it++) {
            cp16(ab + (a_row[it] * AS_STR + a_c4[it]) * 4,
                 A + (size_t)(row0 + a_row[it]) * K + a_c4[it]);
            cp16(bb + (b_k[it] * BS_STR + b_n4[it]) * 4,
                 W + (size_t)b_k[it] * N + col0 + b_n4[it]);
        }
        CP_COMMIT();
    }

    for (int ic = 0; ic < nchunk; ic++) {
        const int p = ic & 1;
        CP_WAIT0();
        __syncthreads();
        if (ic + 1 < nchunk) {
            const int k1 = (ic + 1) << 5;
            const uint32_t ab = smb + (p ? 0 : BUF_FLTS * 4);
            const uint32_t bb = ab + A_FLTS * 4;
#pragma unroll
            for (int it = 0; it < 8; it++) {
                cp16(ab + (a_row[it] * AS_STR + a_c4[it]) * 4,
                     A + (size_t)(row0 + a_row[it]) * K + k1 + a_c4[it]);
                cp16(bb + (b_k[it] * BS_STR + b_n4[it]) * 4,
                     W + (size_t)(k1 + b_k[it]) * N + col0 + b_n4[it]);
            }
            CP_COMMIT();
        }

        const float* sA = sm + (p ? BUF_FLTS : 0);
        const float* sB = sA + A_FLTS;
#pragma unroll
        for (int ks = 0; ks < 4; ks++) {
            const int k8 = ks * 8;
            uint32_t af[4][4];
#pragma unroll
            for (int mt = 0; mt < 4; mt++) {
                const int r = wm + mt * 16 + g;
                af[mt][0] = __float_as_uint(sA[r * AS_STR + k8 + t]);
                af[mt][1] = __float_as_uint(sA[(r + 8) * AS_STR + k8 + t]);
                af[mt][2] = __float_as_uint(sA[r * AS_STR + k8 + 4 + t]);
                af[mt][3] = __float_as_uint(sA[(r + 8) * AS_STR + k8 + 4 + t]);
            }
            uint32_t bf[8][2];
#pragma unroll
            for (int nt = 0; nt < 8; nt++) {
                const int n = wn + nt * 8 + g;
                bf[nt][0] = __float_as_uint(sB[(k8 + t) * BS_STR + n]);
                bf[nt][1] = __float_as_uint(sB[(k8 + 4 + t) * BS_STR + n]);
            }
#pragma unroll
            for (int mt = 0; mt < 4; mt++)
#pragma unroll
                for (int nt = 0; nt < 8; nt++)
                    mma_tf32(acc[mt][nt], af[mt][0], af[mt][1], af[mt][2], af[mt][3],
                             bf[nt][0], bf[nt][1]);
        }
    }

#pragma unroll
    for (int mt = 0; mt < 4; mt++) {
        const int ra = row0 + wm + mt * 16 + g;
#pragma unroll
        for (int nt = 0; nt < 8; nt++) {
            const int cc = col0 + wn + nt * 8 + 2 * t;
            float2 bv = *(const float2*)(bias + cc);
            float v0 = acc[mt][nt][0] + bv.x;
            float v1 = acc[mt][nt][1] + bv.y;
            float v2 = acc[mt][nt][2] + bv.x;
            float v3 = acc[mt][nt][3] + bv.y;
            if (RELU) {
                v0 = fmaxf(v0, 0.f); v1 = fmaxf(v1, 0.f);
                v2 = fmaxf(v2, 0.f); v3 = fmaxf(v3, 0.f);
            }
            if (round_out) {
                v0 = rnd_tf32(v0); v1 = rnd_tf32(v1);
                v2 = rnd_tf32(v2); v3 = rnd_tf32(v3);
            }
            *(float2*)(C + (size_t)ra * N + cc) = make_float2(v0, v1);
            *(float2*)(C + (size_t)(ra + 8) * N + cc) = make_float2(v2, v3);
        }
    }
}

template<bool RELU>
__global__ void __launch_bounds__(128, 2) gemm_ca(
    const float* __restrict__ A, const float* __restrict__ W,
    const float* __restrict__ bias, float* __restrict__ C,
    int N, int K, int round_out)
{
    extern __shared__ float sm[];
    gemm_body<RELU>(A, W, bias, C, N, K, round_out != 0,
                    sm, blockIdx.y * 128, blockIdx.x * 128);
}

// Batched QKV projection: z in {0,1,2} selects (A, W, bias, C, round flag).
struct QKV {
    const float* A[3];
    const float* W[3];
    const float* b[3];
    float* C[3];
    int round_flag[3];
};

__global__ void __launch_bounds__(128, 2) gemm_qkv(QKV q)
{
    extern __shared__ float sm[];
    const int z = blockIdx.z;
    gemm_body<false>(q.A[z], q.W[z], q.b[z], q.C[z], DD, DD,
                     q.round_flag[z] != 0, sm, blockIdx.y * 128, blockIdx.x * 128);
}

// ============================================================================
// Attention logits: out = QK^T/8 + mask. Q split hi/lo (exact), K plain tf32.
// CTA 128x128 per (bh), K=64 one shot. SMEM 104.4KB -> 2 CTAs/SM.
// ============================================================================
#define L2_STR 68
#define LOG_SMEM_BYTES (3*128*L2_STR*4)   // 104448

__global__ void __launch_bounds__(256, 2) attn_logits2(
    const float* __restrict__ q, const float* __restrict__ k,
    const float* __restrict__ mask, float* __restrict__ out)
{
    extern __shared__ float sm[];
    float* Qhi = sm;
    float* Qlo = Qhi + 128 * L2_STR;
    float* Ks  = Qlo + 128 * L2_STR;
    const uint32_t ks_u32 = smem_u32(Ks);

    const int tid = threadIdx.x;
    const int wid = tid >> 5, lane = tid & 31;
    const int g = lane >> 2, t = lane & 3;
    const int wm = (wid >> 1) * 32;
    const int wn = (wid & 1) * 64;

    const int bh = blockIdx.z;
    const int b = bh >> 4, h = bh & 15;
    const int row0 = blockIdx.y * 128, col0 = blockIdx.x * 128;
    const float* qb = q + (size_t)b * SS * DD + h * DH;
    const float* kb = k + (size_t)b * SS * DD + h * DH;

#pragma unroll
    for (int it = 0; it < 8; it++) {
        const int lin = it * 256 + tid;
        const int n = lin >> 4, c4 = (lin & 15) * 4;
        cp16(ks_u32 + (n * L2_STR + c4) * 4,
             kb + (size_t)(col0 + n) * DD + c4);
    }
    CP_COMMIT();

#pragma unroll
    for (int it = 0; it < 8; it++) {
        const int lin = it * 256 + tid;
        const int r = lin >> 4, c4 = (lin & 15) * 4;
        float4 v = *(const float4*)(qb + (size_t)(row0 + r) * DD + c4);
        float vv[4] = {v.x, v.y, v.z, v.w};
#pragma unroll
        for (int j = 0; j < 4; j++) {
            float hi = rnd_tf32(vv[j]);
            Qhi[r * L2_STR + c4 + j] = hi;
            Qlo[r * L2_STR + c4 + j] = rnd_tf32(vv[j] - hi);
        }
    }
    CP_WAIT0();
    __syncthreads();

    float acc[2][8][4];
#pragma unroll
    for (int mt = 0; mt < 2; mt++)
#pragma unroll
        for (int nt = 0; nt < 8; nt++)
#pragma unroll
            for (int i = 0; i < 4; i++) acc[mt][nt][i] = 0.f;

#pragma unroll
    for (int ks = 0; ks < 8; ks++) {
        const int k8 = ks * 8;
        uint32_t ah[2][4], al[2][4];
#pragma unroll
        for (int mt = 0; mt < 2; mt++) {
            const int r = wm + mt * 16 + g;
            ah[mt][0] = __float_as_uint(Qhi[r * L2_STR + k8 + t]);
            ah[mt][1] = __float_as_uint(Qhi[(r + 8) * L2_STR + k8 + t]);
            ah[mt][2] = __float_as_uint(Qhi[r * L2_STR + k8 + 4 + t]);
            ah[mt][3] = __float_as_uint(Qhi[(r + 8) * L2_STR + k8 + 4 + t]);
            al[mt][0] = __float_as_uint(Qlo[r * L2_STR + k8 + t]);
            al[mt][1] = __float_as_uint(Qlo[(r + 8) * L2_STR + k8 + t]);
            al[mt][2] = __float_as_uint(Qlo[r * L2_STR + k8 + 4 + t]);
            al[mt][3] = __float_as_uint(Qlo[(r + 8) * L2_STR + k8 + 4 + t]);
        }
#pragma unroll
        for (int nt = 0; nt < 8; nt++) {
            const int n = wn + nt * 8 + g;
            uint32_t b0 = __float_as_uint(Ks[n * L2_STR + k8 + t]);
            uint32_t b1 = __float_as_uint(Ks[n * L2_STR + k8 + 4 + t]);
#pragma unroll
            for (int mt = 0; mt < 2; mt++) {
                mma_tf32(acc[mt][nt], al[mt][0], al[mt][1], al[mt][2], al[mt][3], b0, b1);
                mma_tf32(acc[mt][nt], ah[mt][0], ah[mt][1], ah[mt][2], ah[mt][3], b0, b1);
            }
        }
    }

    const float* mb = mask + (size_t)b * SS * SS;
    float* ob = out + (size_t)bh * SS * SS;
#pragma unroll
    for (int mt = 0; mt < 2; mt++) {
        const int r = row0 + wm + mt * 16 + g;
#pragma unroll
        for (int nt = 0; nt < 8; nt++) {
            const int c = col0 + wn + nt * 8 + 2 * t;
            float2 m0 = *(const float2*)(mb + (size_t)r * SS + c);
            float2 m1 = *(const float2*)(mb + (size_t)(r + 8) * SS + c);
            *(float2*)(ob + (size_t)r * SS + c) =
                make_float2(acc[mt][nt][0] * 0.125f + m0.x,
                            acc[mt][nt][1] * 0.125f + m0.y);
            *(float2*)(ob + (size_t)(r + 8) * SS + c) =
                make_float2(acc[mt][nt][2] * 0.125f + m1.x,
                            acc[mt][nt][3] * 0.125f + m1.y);
        }
    }
}

// ============================================================================
// Batched AV w/ cp.async. Race-free pipeline. CTA 128x64, warp 32x32.
// ============================================================================
#define AVA_STR 36
#define AVB_STR 72
#define AV_A_FLTS (128*AVA_STR)
#define AV_B_FLTS (32*AVB_STR)
#define AV_BUF (AV_A_FLTS + AV_B_FLTS)   // 6912
#define AV_SMEM_BYTES (2*AV_BUF*4)       // 55296

__global__ void __launch_bounds__(256, 2) attn_av_ca(
    const float* __restrict__ w, const float* __restrict__ v,
    float* __restrict__ ctx)
{
    extern __shared__ float sm[];
    const uint32_t smb = smem_u32(sm);
    const int tid = threadIdx.x;
    const int wid = tid >> 5, lane = tid & 31;
    const int g = lane >> 2, t = lane & 3;
    const int wm = (wid >> 1) * 32;
    const int wn = (wid & 1) * 32;

    const int bh = blockIdx.y;
    const int b = bh >> 4, h = bh & 15;
    const int row0 = blockIdx.x * 128;
    const float* wb = w + (size_t)bh * SS * SS;
    const float* vb = v + (size_t)b * SS * DD + h * DH;

    int a_row[4], a_c4[4], b_k[2], b_n4[2];
#pragma unroll
    for (int it = 0; it < 4; it++) {
        int lin = it * 256 + tid;
        a_row[it] = lin >> 3;
        a_c4[it]  = (lin & 7) * 4;
    }
#pragma unroll
    for (int it = 0; it < 2; it++) {
        int lin = it * 256 + tid;
        b_k[it]  = lin >> 4;
        b_n4[it] = (lin & 15) * 4;
    }

    float acc[2][4][4];
#pragma unroll
    for (int mt = 0; mt < 2; mt++)
#pragma unroll
        for (int nt = 0; nt < 4; nt++)
#pragma unroll
            for (int i = 0; i < 4; i++) acc[mt][nt][i] = 0.f;

    {
        const uint32_t ab = smb, bb = smb + AV_A_FLTS * 4;
#pragma unroll
        for (int it = 0; it < 4; it++)
            cp16(ab + (a_row[it] * AVA_STR + a_c4[it]) * 4,
                 wb + (size_t)(row0 + a_row[it]) * SS + a_c4[it]);
#pragma unroll
        for (int it = 0; it < 2; it++)
            cp16(bb + (b_k[it] * AVB_STR + b_n4[it]) * 4,
                 vb + (size_t)b_k[it] * DD + b_n4[it]);
        CP_COMMIT();
    }

    for (int ic = 0; ic < 32; ic++) {
        const int p = ic & 1;
        CP_WAIT0();
        __syncthreads();
        if (ic + 1 < 32) {
            const int k1 = (ic + 1) << 5;
            const uint32_t ab = smb + (p ? 0 : AV_BUF * 4);
            const uint32_t bb = ab + AV_A_FLTS * 4;
#pragma unroll
            for (int it = 0; it < 4; it++)
                cp16(ab + (a_row[it] * AVA_STR + a_c4[it]) * 4,
                     wb + (size_t)(row0 + a_row[it]) * SS + k1 + a_c4[it]);
#pragma unroll
            for (int it = 0; it < 2; it++)
                cp16(bb + (b_k[it] * AVB_STR + b_n4[it]) * 4,
                     vb + (size_t)(k1 + b_k[it]) * DD + b_n4[it]);
            CP_COMMIT();
        }

        const float* sA = sm + (p ? AV_BUF : 0);
        const float* sB = sA + AV_A_FLTS;
#pragma unroll
        for (int ks = 0; ks < 4; ks++) {
            const int k8 = ks * 8;
            uint32_t af[2][4];
#pragma unroll
            for (int mt = 0; mt < 2; mt++) {
                const int r = wm + mt * 16 + g;
                af[mt][0] = __float_as_uint(sA[r * AVA_STR + k8 + t]);
                af[mt][1] = __float_as_uint(sA[(r + 8) * AVA_STR + k8 + t]);
                af[mt][2] = __float_as_uint(sA[r * AVA_STR + k8 + 4 + t]);
                af[mt][3] = __float_as_uint(sA[(r + 8) * AVA_STR + k8 + 4 + t]);
            }
            uint32_t bf[4][2];
#pragma unroll
            for (int nt = 0; nt < 4; nt++) {
                const int n = wn + nt * 8 + g;
                bf[nt][0] = __float_as_uint(sB[(k8 + t) * AVB_STR + n]);
                bf[nt][1] = __float_as_uint(sB[(k8 + 4 + t) * AVB_STR + n]);
            }
#pragma unroll
            for (int mt = 0; mt < 2; mt++)
#pragma unroll
                for (int nt = 0; nt < 4; nt++)
                    mma_tf32(acc[mt][nt], af[mt][0], af[mt][1], af[mt][2], af[mt][3],
                             bf[nt][0], bf[nt][1]);
        }
    }

#pragma unroll
    for (int mt = 0; mt < 2; mt++) {
        const int ra = row0 + wm + mt * 16 + g;
#pragma unroll
        for (int nt = 0; nt < 4; nt++) {
            const int cc = wn + nt * 8 + 2 * t;
            float* dst0 = ctx + (size_t)(b * SS + ra) * DD + h * DH + cc;
            float* dst1 = ctx + (size_t)(b * SS + ra + 8) * DD + h * DH + cc;
            *(float2*)dst0 = make_float2(rnd_tf32(acc[mt][nt][0]), rnd_tf32(acc[mt][nt][1]));
            *(float2*)dst1 = make_float2(rnd_tf32(acc[mt][nt][2]), rnd_tf32(acc[mt][nt][3]));
        }
    }
}

// ============================================================================
// Softmax: warp-per-row (8 rows/block). Each lane owns 8 float4 (32 values)
// covering the FULL 1024-wide row. __expf; writes tf32-rounded weights.
// ============================================================================
__global__ __launch_bounds__(256) void softmax_rows_w(float* __restrict__ w)
{
    const int row = blockIdx.x * 8 + (threadIdx.x >> 5);
    const int lane = threadIdx.x & 31;
    float* p = w + (size_t)row * SS;

    float4 v[8];
#pragma unroll
    for (int j = 0; j < 8; j++)
        v[j] = *(const float4*)(p + lane * 4 + j * 128);

    float m = -1e30f;
#pragma unroll
    for (int j = 0; j < 8; j++)
        m = fmaxf(m, fmaxf(fmaxf(v[j].x, v[j].y), fmaxf(v[j].z, v[j].w)));
#pragma unroll
    for (int o = 16; o; o >>= 1) m = fmaxf(m, __shfl_xor_sync(0xffffffffu, m, o));

    float s = 0.f;
#pragma unroll
    for (int j = 0; j < 8; j++) {
        v[j].x = __expf(v[j].x - m); v[j].y = __expf(v[j].y - m);
        v[j].z = __expf(v[j].z - m); v[j].w = __expf(v[j].w - m);
        s += (v[j].x + v[j].y) + (v[j].z + v[j].w);
    }
#pragma unroll
    for (int o = 16; o; o >>= 1) s += __shfl_xor_sync(0xffffffffu, s, o);
    const float inv = 1.f / s;

#pragma unroll
    for (int j = 0; j < 8; j++) {
        float4 o4;
        o4.x = rnd_tf32(v[j].x * inv); o4.y = rnd_tf32(v[j].y * inv);
        o4.z = rnd_tf32(v[j].z * inv); o4.w = rnd_tf32(v[j].w * inv);
        *(float4*)(p + lane * 4 + j * 128) = o4;
    }
}

// ============================================================================
// Fused residual add + LayerNorm; optional tf32-rounded twin output.
// ============================================================================
__global__ __launch_bounds__(256) void add_ln(
    const float* __restrict__ a, const float* __restrict__ r,
    const float* __restrict__ g, const float* __restrict__ beta,
    float* __restrict__ out, float* __restrict__ outr)
{
    const size_t base = (size_t)blockIdx.x * DD;
    const int tid = threadIdx.x;
    float4 va = *(const float4*)(a + base + tid * 4);
    float4 vr = *(const float4*)(r + base + tid * 4);
    float x0 = va.x + vr.x, x1 = va.y + vr.y, x2 = va.z + vr.z, x3 = va.w + vr.w;

    float s = x0 + x1 + x2 + x3;
    float sq = x0 * x0 + x1 * x1 + x2 * x2 + x3 * x3;
#pragma unroll
    for (int o = 16; o; o >>= 1) {
        s  += __shfl_xor_sync(0xffffffffu, s, o);
        sq += __shfl_xor_sync(0xffffffffu, sq, o);
    }
    __shared__ float ss[8], ssq[8];
    if ((tid & 31) == 0) { ss[tid >> 5] = s; ssq[tid >> 5] = sq; }
    __syncthreads();
    float ts = 0.f, tsq = 0.f;
#pragma unroll
    for (int i = 0; i < 8; i++) { ts += ss[i]; tsq += ssq[i]; }
    const float mu = ts * (1.0f / DD);
    const float var = tsq * (1.0f / DD) - mu * mu;
    const float rs = rsqrtf(var + LN_EPS);

    float4 gg = *(const float4*)(g + tid * 4);
    float4 bb = *(const float4*)(beta + tid * 4);
    float4 o4;
    o4.x = (x0 - mu) * rs * gg.x + bb.x;
    o4.y = (x1 - mu) * rs * gg.y + bb.y;
    o4.z = (x2 - mu) * rs * gg.z + bb.z;
    o4.w = (x3 - mu) * rs * gg.w + bb.w;
    *(float4*)(out + base + tid * 4) = o4;
    if (outr) {
        float4 q4;
        q4.x = rnd_tf32(o4.x); q4.y = rnd_tf32(o4.y);
        q4.z = rnd_tf32(o4.z); q4.w = rnd_tf32(o4.w);
        *(float4*)(outr + base + tid * 4) = q4;
    }
}

// ============================================================================
// Host launch
// ============================================================================
extern "C" void kernel_launch(void* const* d_in, const int* in_sizes, int n_in,
                              void* d_out, int out_size)
{
    (void)in_sizes; (void)n_in; (void)out_size;
    const float* x    = (const float*)d_in[0];
    const float* enc  = (const float*)d_in[1];
    const float* pad  = (const float*)d_in[2];
    const float* sub  = (const float*)d_in[3];
    const float* wq1w = (const float*)d_in[4];   const float* wq1b = (const float*)d_in[5];
    const float* wk1w = (const float*)d_in[6];   const float* wk1b = (const float*)d_in[7];
    const float* wv1w = (const float*)d_in[8];   const float* wv1b = (const float*)d_in[9];
    const float* wo1w = (const float*)d_in[10];  const float* wo1b = (const float*)d_in[11];
    const float* wq2w = (const float*)d_in[12];  const float* wq2b = (const float*)d_in[13];
    const float* wk2w = (const float*)d_in[14];  const float* wk2b = (const float*)d_in[15];
    const float* wv2w = (const float*)d_in[16];  const float* wv2b = (const float*)d_in[17];
    const float* wo2w = (const float*)d_in[18];  const float* wo2b = (const float*)d_in[19];
    const float* f1w  = (const float*)d_in[20];  const float* f1b  = (const float*)d_in[21];
    const float* f2w  = (const float*)d_in[22];  const float* f2b  = (const float*)d_in[23];
    const float* ln1g = (const float*)d_in[24];  const float* ln1b = (const float*)d_in[25];
    const float* ln2g = (const float*)d_in[26];  const float* ln2b = (const float*)d_in[27];
    const float* ln3g = (const float*)d_in[28];  const float* ln3b = (const float*)d_in[29];

    static float *q_p, *k_p, *v_p, *ctx_p, *mha_p, *res1_p, *res2_p, *ffn_p;
    static float *wt_p, *xr_p, *encr_p, *res1r_p, *res2r_p;
    static bool init = false;
    if (!init) {
        cudaGetSymbolAddress((void**)&q_p, g_q);
        cudaGetSymbolAddress((void**)&k_p, g_k);
        cudaGetSymbolAddress((void**)&v_p, g_v);
        cudaGetSymbolAddress((void**)&ctx_p, g_ctx);
        cudaGetSymbolAddress((void**)&mha_p, g_mha);
        cudaGetSymbolAddress((void**)&res1_p, g_res1);
        cudaGetSymbolAddress((void**)&res2_p, g_res2);
        cudaGetSymbolAddress((void**)&ffn_p, g_ffn);
        cudaGetSymbolAddress((void**)&wt_p, g_wt);
        cudaGetSymbolAddress((void**)&xr_p, g_xr);
        cudaGetSymbolAddress((void**)&encr_p, g_encr);
        cudaGetSymbolAddress((void**)&res1r_p, g_res1r);
        cudaGetSymbolAddress((void**)&res2r_p, g_res2r);
        cudaFuncSetAttribute(gemm_ca<false>,
            cudaFuncAttributeMaxDynamicSharedMemorySize, GEMM_SMEM_BYTES);
        cudaFuncSetAttribute(gemm_ca<true>,
            cudaFuncAttributeMaxDynamicSharedMemorySize, GEMM_SMEM_BYTES);
        cudaFuncSetAttribute(gemm_qkv,
            cudaFuncAttributeMaxDynamicSharedMemorySize, GEMM_SMEM_BYTES);
        cudaFuncSetAttribute(attn_logits2,
            cudaFuncAttributeMaxDynamicSharedMemorySize, LOG_SMEM_BYTES);
        cudaFuncSetAttribute(attn_av_ca,
            cudaFuncAttributeMaxDynamicSharedMemorySize, AV_SMEM_BYTES);
        init = true;
    }

    // rounded weight slots (floats)
    const size_t M1 = 1024u * 1024u;
    float* t_q1 = wt_p + 0*M1;  float* t_k1 = wt_p + 1*M1;
    float* t_v1 = wt_p + 2*M1;  float* t_o1 = wt_p + 3*M1;
    float* t_q2 = wt_p + 4*M1;  float* t_k2 = wt_p + 5*M1;
    float* t_v2 = wt_p + 6*M1;  float* t_o2 = wt_p + 7*M1;
    float* t_f1 = wt_p + 8*M1;
    float* t_f2 = wt_p + 12*M1;

    // Output layout: out3 | attn_w1 | attn_w2
    float* out3 = (float*)d_out;
    float* aw1  = out3 + (size_t)MM * DD;
    float* aw2  = aw1 + (size_t)BB * HH * SS * SS;

    // ---- merged rounding (one launch) ----
    R12 r12;
    const float* srcs[12] = {wq1w, wk1w, wv1w, wo1w, wq2w, wk2w, wv2w, wo2w,
                             f1w, f2w, x, enc};
    float* dsts[12] = {t_q1, t_k1, t_v1, t_o1, t_q2, t_k2, t_v2, t_o2,
                       t_f1, t_f2, xr_p, encr_p};
    int blks[12] = {256,256,256,256,256,256,256,256,1024,1024,1024,1024};
    int c = 0;
    for (int i = 0; i < 12; i++) {
        r12.src[i] = (const float4*)srcs[i];
        r12.dst[i] = (float4*)dsts[i];
        r12.cum[i] = c;
        c += blks[i];
    }
    r12.cum[12] = c;   // 6144
    round_all<<<c, 256>>>(r12);

    const dim3 gD(DD / 128, MM / 128);
    const dim3 gF(DFF / 128, MM / 128);
    const dim3 gQKV(DD / 128, MM / 128, 3);
    const dim3 gLog(SS / 128, SS / 128, BB * HH);
    const dim3 gAV(SS / 128, BB * HH);
    const int nSmBlocks = BB * HH * SS / 8;   // 8192

    // ---- MHA1 (self-attention) ----
    {
        QKV qk;
        qk.A[0] = xr_p; qk.A[1] = xr_p; qk.A[2] = xr_p;
        qk.W[0] = t_q1; qk.W[1] = t_k1; qk.W[2] = t_v1;
        qk.b[0] = wq1b; qk.b[1] = wk1b; qk.b[2] = wv1b;
        qk.C[0] = q_p;  qk.C[1] = k_p;  qk.C[2] = v_p;
        qk.round_flag[0] = 0; qk.round_flag[1] = 1; qk.round_flag[2] = 1;
        gemm_qkv<<<gQKV, 128, GEMM_SMEM_BYTES>>>(qk);
    }
    attn_logits2<<<gLog, 256, LOG_SMEM_BYTES>>>(q_p, k_p, sub, aw1);
    softmax_rows_w<<<nSmBlocks, 256>>>(aw1);
    attn_av_ca<<<gAV, 256, AV_SMEM_BYTES>>>(aw1, v_p, ctx_p);
    gemm_ca<false><<<gD, 128, GEMM_SMEM_BYTES>>>(ctx_p, t_o1, wo1b, mha_p, DD, DD, 0);
    add_ln<<<MM, 256>>>(mha_p, x, ln1g, ln1b, res1_p, res1r_p);

    // ---- MHA2 (cross-attention) ----
    {
        QKV qk;
        qk.A[0] = res1r_p; qk.A[1] = encr_p; qk.A[2] = encr_p;
        qk.W[0] = t_q2; qk.W[1] = t_k2; qk.W[2] = t_v2;
        qk.b[0] = wq2b; qk.b[1] = wk2b; qk.b[2] = wv2b;
        qk.C[0] = q_p;  qk.C[1] = k_p;  qk.C[2] = v_p;
        qk.round_flag[0] = 0; qk.round_flag[1] = 1; qk.round_flag[2] = 1;
        gemm_qkv<<<gQKV, 128, GEMM_SMEM_BYTES>>>(qk);
    }
    attn_logits2<<<gLog, 256, LOG_SMEM_BYTES>>>(q_p, k_p, pad, aw2);
    softmax_rows_w<<<nSmBlocks, 256>>>(aw2);
    attn_av_ca<<<gAV, 256, AV_SMEM_BYTES>>>(aw2, v_p, ctx_p);
    gemm_ca<false><<<gD, 128, GEMM_SMEM_BYTES>>>(ctx_p, t_o2, wo2b, mha_p, DD, DD, 0);
    add_ln<<<MM, 256>>>(mha_p, res1_p, ln2g, ln2b, res2_p, res2r_p);

    // ---- FFN ----
    gemm_ca<true ><<<gF, 128, GEMM_SMEM_BYTES>>>(res2r_p, t_f1, f1b, ffn_p, DFF, DD, 1);
    gemm_ca<false><<<gD, 128, GEMM_SMEM_BYTES>>>(ffn_p, t_f2, f2b, mha_p, DD, DFF, 0);
    add_ln<<<MM, 256>>>(mha_p, res2_p, ln3g, ln3b, out3, nullptr);
}